// round 1
// baseline (speedup 1.0000x reference)
#include <cuda_runtime.h>
#include <math.h>

// Problem constants (fixed shapes from reference)
#define H 112
#define W 112
#define HW 12544
#define CIN 64
#define OUTC 64
#define NB 8
#define NOFF 27          // 3*K*K
#define KK 576           // CIN * 9

// Scratch (static __device__ — no runtime allocation)
__device__ float g_raw[NB * NOFF * HW];   // offset-conv output [N][27][H][W]
__device__ float g_wt[KK * OUTC];         // weight transposed  [k][o], k = c*9+t
__device__ float g_owt[KK * 32];          // offset_w transposed [k][oc], padded oc->32

__device__ __forceinline__ void fma4(float4& a, float s, const float4 w) {
    a.x = fmaf(s, w.x, a.x);
    a.y = fmaf(s, w.y, a.y);
    a.z = fmaf(s, w.z, a.z);
    a.w = fmaf(s, w.w, a.w);
}

// ---------------------------------------------------------------------------
// Kernel 0: transpose weights into k-major layouts
// ---------------------------------------------------------------------------
__global__ void k_transpose(const float* __restrict__ w, const float* __restrict__ ow) {
    int idx = blockIdx.x * 256 + threadIdx.x;
    if (idx < KK * OUTC) {
        int k = idx >> 6, o = idx & 63;
        g_wt[k * 64 + o] = w[o * KK + k];
    }
    if (idx < KK * 32) {
        int k = idx >> 5, oc = idx & 31;
        g_owt[idx] = (oc < NOFF) ? ow[oc * KK + k] : 0.f;
    }
}

// ---------------------------------------------------------------------------
// Kernel 1: offset predictor conv (3x3, pad 1) -> g_raw, bias folded in.
// Tile: 16 wo x 8 ho per block, 256 threads.
// Thread map: g = tid>>5 (oc group of 4, padded to 8 groups), lane: qx=lane&3
// (4-wide wo quad), y=lane>>2 (8 ho rows). Each thread: 4 oc x 4 px accums.
// ---------------------------------------------------------------------------
__global__ void k_offset(const float* __restrict__ x, const float* __restrict__ ob) {
    extern __shared__ float xs[];   // [64][10][20] : rows 10 = 8+2 halo, cols 18 used (pad 20)
    const int tid = threadIdx.x;
    const int wo0 = blockIdx.x * 16, ho0 = blockIdx.y * 8, n = blockIdx.z;
    const float* xn = x + (size_t)n * CIN * HW;

    // cooperative load of the input patch (zero-padded halo)
    for (int idx = tid; idx < 64 * 10 * 18; idx += 256) {
        int c = idx / 180;
        int rem = idx - c * 180;
        int r = rem / 18;
        int col = rem - r * 18;
        int gy = ho0 - 1 + r, gx = wo0 - 1 + col;
        float v = 0.f;
        if (gy >= 0 && gy < H && gx >= 0 && gx < W) v = xn[c * HW + gy * W + gx];
        xs[(c * 10 + r) * 20 + col] = v;
    }
    __syncthreads();

    const int g = tid >> 5;
    if (g == 7) return;   // group 7 is all padding oc (28..31); done after coop load

    const int lane = tid & 31;
    const int qx = lane & 3, y = lane >> 2;
    const int wx = qx * 4;

    float4 acc[4];
    acc[0] = acc[1] = acc[2] = acc[3] = make_float4(0.f, 0.f, 0.f, 0.f);
    const float4* owt4 = (const float4*)g_owt;   // [KK][8] float4

    for (int c = 0; c < 64; c++) {
        #pragma unroll
        for (int dy = 0; dy < 3; dy++) {
            const float* row = &xs[(c * 10 + y + dy) * 20 + wx];
            float4 rv = *(const float4*)row;
            float2 rv2 = *(const float2*)(row + 4);
            float r0 = rv.x, r1 = rv.y, r2 = rv.z, r3 = rv.w, r4 = rv2.x, r5 = rv2.y;
            int kb = c * 9 + dy * 3;
            float4 w0 = owt4[(kb + 0) * 8 + g];
            float4 w1 = owt4[(kb + 1) * 8 + g];
            float4 w2 = owt4[(kb + 2) * 8 + g];
            fma4(acc[0], r0, w0); fma4(acc[1], r1, w0); fma4(acc[2], r2, w0); fma4(acc[3], r3, w0);
            fma4(acc[0], r1, w1); fma4(acc[1], r2, w1); fma4(acc[2], r3, w1); fma4(acc[3], r4, w1);
            fma4(acc[0], r2, w2); fma4(acc[1], r3, w2); fma4(acc[2], r4, w2); fma4(acc[3], r5, w2);
        }
    }

    const float* af = (const float*)acc;   // af[j*4+comp]
    const int ho = ho0 + y;
    #pragma unroll
    for (int comp = 0; comp < 4; comp++) {
        int oc = g * 4 + comp;
        if (oc >= NOFF) break;
        float b = ob[oc];
        float4 o4 = make_float4(af[comp] + b, af[4 + comp] + b, af[8 + comp] + b, af[12 + comp] + b);
        *(float4*)&g_raw[(((size_t)n * NOFF + oc) * H + ho) * W + wo0 + wx] = o4;
    }
}

// ---------------------------------------------------------------------------
// Kernel 2: deformable sampling + modulated conv (GEMM).
// Tile: 16 wo x 2 ho = 32 px per block, 128 threads.
// Stage 0: per (tap,px) corner weights (mask folded) + clamped indices -> smem
// Stage 1: gather x, build val[k=c*9+t][px] in smem (73.7 KB)
// Stage 2: GEMM 64o x 576k x 32px; thread = (og 4 o's, pg 4 px's), 16 FMA/k
// ---------------------------------------------------------------------------
__global__ void k_main(const float* __restrict__ x, const float* __restrict__ bias,
                       float* __restrict__ out) {
    extern __shared__ unsigned char sm[];
    float4* cw_s = (float4*)sm;                    // [9][32] corner weights (288 * 16B)
    int4*   ci_s = (int4*)(sm + 4608);             // [9][32] corner flat offsets
    float*  val_s = (float*)(sm + 9216);           // [576][32]

    const int tid = threadIdx.x;
    const int wo0 = blockIdx.x * 16, ho0 = blockIdx.y * 2, n = blockIdx.z;

    // ---- stage 0: corner precompute (9 taps x 32 px = 288 tasks) ----
    for (int idx = tid; idx < 288; idx += 128) {
        int t = idx >> 5, p = idx & 31;
        int y = p >> 4, wxl = p & 15;
        int ho = ho0 + y, wo = wo0 + wxl;
        size_t rbase = (((size_t)n * NOFF) * H + ho) * W + wo;
        float dyv = g_raw[rbase + (size_t)(2 * t) * HW];
        float dxv = g_raw[rbase + (size_t)(2 * t + 1) * HW];
        float mv  = g_raw[rbase + (size_t)(18 + t) * HW];
        float m = 1.f / (1.f + expf(-mv));
        float py = dyv + (float)(ho - 1 + t / 3);
        float px = dxv + (float)(wo - 1 + t % 3);
        float y0f = floorf(py), x0f = floorf(px);
        float wy1 = py - y0f, wy0 = 1.f - wy1;
        float wx1 = px - x0f, wx0 = 1.f - wx1;
        int y0 = (int)y0f, x0 = (int)x0f;
        int y1 = y0 + 1, x1 = x0 + 1;
        bool vy0 = (y0 >= 0) && (y0 < H), vy1 = (y1 >= 0) && (y1 < H);
        bool vx0 = (x0 >= 0) && (x0 < W), vx1 = (x1 >= 0) && (x1 < W);
        float w00 = (vy0 && vx0) ? wy0 * wx0 * m : 0.f;
        float w01 = (vy0 && vx1) ? wy0 * wx1 * m : 0.f;
        float w10 = (vy1 && vx0) ? wy1 * wx0 * m : 0.f;
        float w11 = (vy1 && vx1) ? wy1 * wx1 * m : 0.f;
        int yc0 = min(max(y0, 0), H - 1), yc1 = min(max(y1, 0), H - 1);
        int xc0 = min(max(x0, 0), W - 1), xc1 = min(max(x1, 0), W - 1);
        cw_s[idx] = make_float4(w00, w01, w10, w11);
        ci_s[idx] = make_int4(yc0 * W + xc0, yc0 * W + xc1, yc1 * W + xc0, yc1 * W + xc1);
    }
    __syncthreads();

    // ---- stage 1: bilinear gather into val_s ----
    {
        const int lane = tid & 31;
        const int c0 = (tid >> 5) * 16;          // 4 warps, 16 channels each
        const float* xp0 = x + ((size_t)n * CIN + c0) * HW;
        for (int t = 0; t < 9; t++) {
            float4 w4 = cw_s[t * 32 + lane];
            int4 i4 = ci_s[t * 32 + lane];
            #pragma unroll 4
            for (int cc = 0; cc < 16; cc++) {
                const float* xp = xp0 + cc * HW;
                float v = fmaf(w4.x, xp[i4.x],
                          fmaf(w4.y, xp[i4.y],
                          fmaf(w4.z, xp[i4.z],
                               w4.w * xp[i4.w])));
                val_s[((c0 + cc) * 9 + t) * 32 + lane] = v;
            }
        }
    }
    __syncthreads();

    // ---- stage 2: GEMM out[o][px] = sum_k wt[k][o] * val[k][px] ----
    const int og = tid & 15;        // 4 outputs: o = og*4 + comp
    const int pg = tid >> 4;        // 4 pixels:  px = pg*4 + j
    float4 acc[4];
    acc[0] = acc[1] = acc[2] = acc[3] = make_float4(0.f, 0.f, 0.f, 0.f);
    const float4* wt4 = (const float4*)g_wt;     // [KK][16] float4
    const float* vs = val_s + pg * 4;
    #pragma unroll 4
    for (int k = 0; k < KK; k++) {
        float4 w4 = wt4[k * 16 + og];
        float4 v4 = *(const float4*)&vs[k * 32];
        fma4(acc[0], v4.x, w4);
        fma4(acc[1], v4.y, w4);
        fma4(acc[2], v4.z, w4);
        fma4(acc[3], v4.w, w4);
    }

    float4 b4 = ((const float4*)bias)[og];
    const float* bf = (const float*)&b4;
    const float* af = (const float*)acc;         // af[j*4+comp]
    const int ho = ho0 + (pg >> 2);
    const int wo = wo0 + (pg & 3) * 4;
    #pragma unroll
    for (int comp = 0; comp < 4; comp++) {
        int o = og * 4 + comp;
        float b = bf[comp];
        float4 o4 = make_float4(af[comp] + b, af[4 + comp] + b,
                                af[8 + comp] + b, af[12 + comp] + b);
        *(float4*)&out[(((size_t)n * OUTC + o) * H + ho) * W + wo] = o4;
    }
}

// ---------------------------------------------------------------------------
extern "C" void kernel_launch(void* const* d_in, const int* in_sizes, int n_in,
                              void* d_out, int out_size) {
    (void)in_sizes; (void)n_in; (void)out_size;
    const float* x        = (const float*)d_in[0];
    const float* weight   = (const float*)d_in[1];
    const float* bias     = (const float*)d_in[2];
    const float* offset_w = (const float*)d_in[3];
    const float* offset_b = (const float*)d_in[4];
    float* out = (float*)d_out;

    // >48KB dynamic smem needs the attribute; idempotent, safe under capture.
    cudaFuncSetAttribute(k_offset, cudaFuncAttributeMaxDynamicSharedMemorySize, 51200);
    cudaFuncSetAttribute(k_main,   cudaFuncAttributeMaxDynamicSharedMemorySize, 82944);

    k_transpose<<<144, 256>>>(weight, offset_w);
    k_offset<<<dim3(7, 14, 8), 256, 51200>>>(x, offset_b);
    k_main<<<dim3(7, 56, 8), 128, 82944>>>(x, bias, out);
}

// round 2
// speedup vs baseline: 1.4051x; 1.4051x over previous
#include <cuda_runtime.h>
#include <math.h>

// Problem constants (fixed shapes from reference)
#define H 112
#define W 112
#define HW 12544
#define CIN 64
#define OUTC 64
#define NB 8
#define NOFF 27          // 3*K*K
#define KK 576           // CIN * 9

// Scratch (static __device__ — no runtime allocation)
__device__ float g_raw[NB * NOFF * HW];                 // offset-conv output [N][27][H][W]
__device__ __align__(16) float g_xt[NB * HW * CIN];     // x in NHWC [N][H][W][C]
__device__ __align__(16) float g_wt2[KK * 128];         // weights, k'=t*64+c, [k'][o dup pairs]
__device__ float g_owt[KK * 32];                        // offset_w transposed [k][oc], k=c*9+t

__device__ __forceinline__ void fma4(float4& a, float s, const float4 w) {
    a.x = fmaf(s, w.x, a.x);
    a.y = fmaf(s, w.y, a.y);
    a.z = fmaf(s, w.z, a.z);
    a.w = fmaf(s, w.w, a.w);
}

#define FMA2(d, a, b) asm("fma.rn.f32x2 %0, %1, %2, %3;" : "=l"(d) : "l"(a), "l"(b), "l"(d))

// ---------------------------------------------------------------------------
// Kernel 0: weight layouts.
//  g_wt2[(t*64+c)*128 + o*2 + {0,1}] = weight[o][c][t]  (duplicated pairs for f32x2)
//  g_owt[(c*9+t)*32 + oc]            = offset_w[oc][c][t] (padded oc->32)
// ---------------------------------------------------------------------------
__global__ void k_transpose(const float* __restrict__ w, const float* __restrict__ ow) {
    int idx = blockIdx.x * 256 + threadIdx.x;
    if (idx < KK * 64) {
        int k = idx >> 6, o = idx & 63;        // k' = t*64 + c
        int t = k >> 6, c = k & 63;
        float v = w[o * KK + c * 9 + t];
        g_wt2[k * 128 + o * 2]     = v;
        g_wt2[k * 128 + o * 2 + 1] = v;
    }
    if (idx < KK * 32) {
        int k = idx >> 5, oc = idx & 31;
        g_owt[idx] = (oc < NOFF) ? ow[oc * KK + k] : 0.f;
    }
}

// ---------------------------------------------------------------------------
// Kernel 1: NCHW -> NHWC transpose of x (per batch; 64 x 12544 2D transpose)
// ---------------------------------------------------------------------------
__global__ void k_nhwc(const float* __restrict__ x) {
    __shared__ float tile[32][33];
    const int n = blockIdx.z;
    const int c0 = blockIdx.y * 32, p0 = blockIdx.x * 32;
    const float* xn = x + (size_t)n * CIN * HW;
    float* xtn = g_xt + (size_t)n * HW * CIN;
    const int tx = threadIdx.x & 31, ty = threadIdx.x >> 5;   // 32x8
    #pragma unroll
    for (int i = 0; i < 32; i += 8)
        tile[ty + i][tx] = xn[(size_t)(c0 + ty + i) * HW + p0 + tx];
    __syncthreads();
    #pragma unroll
    for (int i = 0; i < 32; i += 8)
        xtn[(size_t)(p0 + ty + i) * CIN + c0 + tx] = tile[tx][ty + i];
}

// ---------------------------------------------------------------------------
// Kernel 2: offset predictor conv (3x3, pad 1) -> g_raw, bias folded in.
// (unchanged from R1; ~FFMA-floor bound, revisit after profiling)
// ---------------------------------------------------------------------------
__global__ void k_offset(const float* __restrict__ x, const float* __restrict__ ob) {
    extern __shared__ float xs[];   // [64][10][20]
    const int tid = threadIdx.x;
    const int wo0 = blockIdx.x * 16, ho0 = blockIdx.y * 8, n = blockIdx.z;
    const float* xn = x + (size_t)n * CIN * HW;

    for (int idx = tid; idx < 64 * 10 * 18; idx += 256) {
        int c = idx / 180;
        int rem = idx - c * 180;
        int r = rem / 18;
        int col = rem - r * 18;
        int gy = ho0 - 1 + r, gx = wo0 - 1 + col;
        float v = 0.f;
        if (gy >= 0 && gy < H && gx >= 0 && gx < W) v = xn[c * HW + gy * W + gx];
        xs[(c * 10 + r) * 20 + col] = v;
    }
    __syncthreads();

    const int g = tid >> 5;
    if (g == 7) return;

    const int lane = tid & 31;
    const int qx = lane & 3, y = lane >> 2;
    const int wx = qx * 4;

    float4 acc[4];
    acc[0] = acc[1] = acc[2] = acc[3] = make_float4(0.f, 0.f, 0.f, 0.f);
    const float4* owt4 = (const float4*)g_owt;   // [KK][8] float4

    for (int c = 0; c < 64; c++) {
        #pragma unroll
        for (int dy = 0; dy < 3; dy++) {
            const float* row = &xs[(c * 10 + y + dy) * 20 + wx];
            float4 rv = *(const float4*)row;
            float2 rv2 = *(const float2*)(row + 4);
            float r0 = rv.x, r1 = rv.y, r2 = rv.z, r3 = rv.w, r4 = rv2.x, r5 = rv2.y;
            int kb = c * 9 + dy * 3;
            float4 w0 = owt4[(kb + 0) * 8 + g];
            float4 w1 = owt4[(kb + 1) * 8 + g];
            float4 w2 = owt4[(kb + 2) * 8 + g];
            fma4(acc[0], r0, w0); fma4(acc[1], r1, w0); fma4(acc[2], r2, w0); fma4(acc[3], r3, w0);
            fma4(acc[0], r1, w1); fma4(acc[1], r2, w1); fma4(acc[2], r3, w1); fma4(acc[3], r4, w1);
            fma4(acc[0], r2, w2); fma4(acc[1], r3, w2); fma4(acc[2], r4, w2); fma4(acc[3], r5, w2);
        }
    }

    const float* af = (const float*)acc;
    const int ho = ho0 + y;
    #pragma unroll
    for (int comp = 0; comp < 4; comp++) {
        int oc = g * 4 + comp;
        if (oc >= NOFF) break;
        float b = ob[oc];
        float4 o4 = make_float4(af[comp] + b, af[4 + comp] + b, af[8 + comp] + b, af[12 + comp] + b);
        *(float4*)&g_raw[(((size_t)n * NOFF + oc) * H + ho) * W + wo0 + wx] = o4;
    }
}

// ---------------------------------------------------------------------------
// Kernel 3: deformable sampling + modulated conv (GEMM).
// Tile: 16 wo x 2 ho = 32 px per block, 128 threads.
// Stage 0: per (tap,px) corner weights (mask folded) + clamped indices -> smem
// Stage 1: NHWC coalesced gather -> val_s[k'=t*64+c][px] (swizzled: px ^ (c&28))
// Stage 2: f32x2 GEMM 64o x 576k x 32px; thread = 4o x 4px, 8 FFMA2 per k
// ---------------------------------------------------------------------------
__global__ void k_main(const float* __restrict__ bias, float* __restrict__ out) {
    extern __shared__ unsigned char sm[];
    float4* cw_s = (float4*)sm;                    // [9][32] corner weights
    int4*   ci_s = (int4*)(sm + 4608);             // [9][32] corner flat pixel indices
    float*  val_s = (float*)(sm + 9216);           // [576][32], swizzled

    const int tid = threadIdx.x;
    const int wo0 = blockIdx.x * 16, ho0 = blockIdx.y * 2, n = blockIdx.z;

    // ---- stage 0: corner precompute (9 taps x 32 px) ----
    for (int idx = tid; idx < 288; idx += 128) {
        int t = idx >> 5, p = idx & 31;
        int y = p >> 4, wxl = p & 15;
        int ho = ho0 + y, wo = wo0 + wxl;
        size_t rbase = (((size_t)n * NOFF) * H + ho) * W + wo;
        float dyv = g_raw[rbase + (size_t)(2 * t) * HW];
        float dxv = g_raw[rbase + (size_t)(2 * t + 1) * HW];
        float mv  = g_raw[rbase + (size_t)(18 + t) * HW];
        float m = 1.f / (1.f + expf(-mv));
        float py = dyv + (float)(ho - 1 + t / 3);
        float px = dxv + (float)(wo - 1 + t % 3);
        float y0f = floorf(py), x0f = floorf(px);
        float wy1 = py - y0f, wy0 = 1.f - wy1;
        float wx1 = px - x0f, wx0 = 1.f - wx1;
        int y0 = (int)y0f, x0 = (int)x0f;
        int y1 = y0 + 1, x1 = x0 + 1;
        bool vy0 = (y0 >= 0) && (y0 < H), vy1 = (y1 >= 0) && (y1 < H);
        bool vx0 = (x0 >= 0) && (x0 < W), vx1 = (x1 >= 0) && (x1 < W);
        float w00 = (vy0 && vx0) ? wy0 * wx0 * m : 0.f;
        float w01 = (vy0 && vx1) ? wy0 * wx1 * m : 0.f;
        float w10 = (vy1 && vx0) ? wy1 * wx0 * m : 0.f;
        float w11 = (vy1 && vx1) ? wy1 * wx1 * m : 0.f;
        int yc0 = min(max(y0, 0), H - 1), yc1 = min(max(y1, 0), H - 1);
        int xc0 = min(max(x0, 0), W - 1), xc1 = min(max(x1, 0), W - 1);
        cw_s[idx] = make_float4(w00, w01, w10, w11);
        ci_s[idx] = make_int4(yc0 * W + xc0, yc0 * W + xc1, yc1 * W + xc0, yc1 * W + xc1);
    }
    __syncthreads();

    // ---- stage 1: coalesced NHWC bilinear gather ----
    {
        const int lane = tid & 31, warp = tid >> 5;
        const int sub = lane >> 4;            // which (t,px) pair of this iteration
        const int c4 = (lane & 15) << 2;      // 4 channels per lane
        const float* xtn = g_xt + (size_t)n * (HW * CIN);
        #pragma unroll 2
        for (int it = 0; it < 36; it++) {
            int p = warp * 72 + it * 2 + sub;    // 0..287
            float4 w4 = cw_s[p];
            int4 i4 = ci_s[p];
            int t = p >> 5, px = p & 31;
            float4 g0 = *(const float4*)(xtn + (size_t)i4.x * CIN + c4);
            float4 g1 = *(const float4*)(xtn + (size_t)i4.y * CIN + c4);
            float4 g2 = *(const float4*)(xtn + (size_t)i4.z * CIN + c4);
            float4 g3 = *(const float4*)(xtn + (size_t)i4.w * CIN + c4);
            float4 v;
            v.x = fmaf(w4.w, g3.x, fmaf(w4.z, g2.x, fmaf(w4.y, g1.x, w4.x * g0.x)));
            v.y = fmaf(w4.w, g3.y, fmaf(w4.z, g2.y, fmaf(w4.y, g1.y, w4.x * g0.y)));
            v.z = fmaf(w4.w, g3.z, fmaf(w4.z, g2.z, fmaf(w4.y, g1.z, w4.x * g0.z)));
            v.w = fmaf(w4.w, g3.w, fmaf(w4.z, g2.w, fmaf(w4.y, g1.w, w4.x * g0.w)));
            int row = (t << 6) + c4;             // k' = t*64 + c
            int spx = px ^ (c4 & 28);            // swizzle (same for c4..c4+3)
            float* vp = val_s + row * 32 + spx;
            vp[0]  = v.x;
            vp[32] = v.y;
            vp[64] = v.z;
            vp[96] = v.w;
        }
    }
    __syncthreads();

    // ---- stage 2: f32x2 GEMM out[o][px] = sum_k wt[k][o] * val[k][px] ----
    const int og = tid & 15;          // o = og*4 + {0..3}
    const int pg = tid >> 4;          // px = pg*4 + {0..3}
    const int pg4 = pg << 2;
    unsigned long long acc[8];        // [o 0..3][px-pair 0..1]
    #pragma unroll
    for (int i = 0; i < 8; i++) acc[i] = 0ULL;

    const ulonglong2* wp = (const ulonglong2*)g_wt2 + og * 2;   // 2 x ulonglong2 per thread per k

    #pragma unroll 4
    for (int k = 0; k < KK; k++) {
        ulonglong2 wv0 = __ldg(wp);          // {w_o0,w_o0},{w_o1,w_o1}
        ulonglong2 wv1 = __ldg(wp + 1);      // {w_o2,w_o2},{w_o3,w_o3}
        const ulonglong2* vpp =
            (const ulonglong2*)(val_s + k * 32 + (pg4 ^ (k & 28)));
        ulonglong2 vv = *vpp;                // {v0,v1},{v2,v3}
        FMA2(acc[0], wv0.x, vv.x); FMA2(acc[1], wv0.x, vv.y);
        FMA2(acc[2], wv0.y, vv.x); FMA2(acc[3], wv0.y, vv.y);
        FMA2(acc[4], wv1.x, vv.x); FMA2(acc[5], wv1.x, vv.y);
        FMA2(acc[6], wv1.y, vv.x); FMA2(acc[7], wv1.y, vv.y);
        wp += 32;                            // 64 ull per k row
    }

    const int ho = ho0 + (pg >> 2);
    const int wo = wo0 + (pg & 3) * 4;
    #pragma unroll
    for (int j = 0; j < 4; j++) {
        int o = og * 4 + j;
        float b = bias[o];
        float4 r;
        asm("mov.b64 {%0,%1}, %2;" : "=f"(r.x), "=f"(r.y) : "l"(acc[j * 2]));
        asm("mov.b64 {%0,%1}, %2;" : "=f"(r.z), "=f"(r.w) : "l"(acc[j * 2 + 1]));
        r.x += b; r.y += b; r.z += b; r.w += b;
        *(float4*)&out[(((size_t)n * OUTC + o) * H + ho) * W + wo] = r;
    }
}

// ---------------------------------------------------------------------------
extern "C" void kernel_launch(void* const* d_in, const int* in_sizes, int n_in,
                              void* d_out, int out_size) {
    (void)in_sizes; (void)n_in; (void)out_size;
    const float* x        = (const float*)d_in[0];
    const float* weight   = (const float*)d_in[1];
    const float* bias     = (const float*)d_in[2];
    const float* offset_w = (const float*)d_in[3];
    const float* offset_b = (const float*)d_in[4];
    float* out = (float*)d_out;

    cudaFuncSetAttribute(k_offset, cudaFuncAttributeMaxDynamicSharedMemorySize, 51200);
    cudaFuncSetAttribute(k_main,   cudaFuncAttributeMaxDynamicSharedMemorySize, 82944);

    k_transpose<<<144, 256>>>(weight, offset_w);
    k_nhwc<<<dim3(392, 2, 8), 256>>>(x);
    k_offset<<<dim3(7, 14, 8), 256, 51200>>>(x, offset_b);
    k_main<<<dim3(7, 56, 8), 128, 82944>>>(bias, out);
}

// round 3
// speedup vs baseline: 2.5762x; 1.8335x over previous
#include <cuda_runtime.h>
#include <math.h>

// Problem constants (fixed shapes from reference)
#define H 112
#define W 112
#define HW 12544
#define CIN 64
#define OUTC 64
#define NB 8
#define NOFF 27          // 3*K*K
#define KK 576           // CIN * 9

// Scratch (static __device__ — no runtime allocation)
__device__ float g_raw[NB * NOFF * HW];                 // offset-conv output [N][27][H][W]
__device__ __align__(16) float g_xt[NB * HW * CIN];     // x in NHWC [N][H][W][C]
__device__ __align__(16) float g_wt2[KK * 128];         // weights, k'=t*64+c, [k'][o dup pairs]
__device__ float g_owt[KK * 32];                        // offset_w transposed [k][oc], k=c*9+t

__device__ __forceinline__ void fma4(float4& a, float s, const float4 w) {
    a.x = fmaf(s, w.x, a.x);
    a.y = fmaf(s, w.y, a.y);
    a.z = fmaf(s, w.z, a.z);
    a.w = fmaf(s, w.w, a.w);
}

#define FMA2(d, a, b) asm("fma.rn.f32x2 %0, %1, %2, %3;" : "=l"(d) : "l"(a), "l"(b), "l"(d))

// ---------------------------------------------------------------------------
// Kernel 0: weight layouts.
//  g_wt2[(t*64+c)*128 + o*2 + {0,1}] = weight[o][c][t]  (duplicated pairs for f32x2)
//  g_owt[(c*9+t)*32 + oc]            = offset_w[oc][c][t] (padded oc->32)
// ---------------------------------------------------------------------------
__global__ void k_transpose(const float* __restrict__ w, const float* __restrict__ ow) {
    int idx = blockIdx.x * 256 + threadIdx.x;
    if (idx < KK * 64) {
        int k = idx >> 6, o = idx & 63;        // k' = t*64 + c
        int t = k >> 6, c = k & 63;
        float v = w[o * KK + c * 9 + t];
        g_wt2[k * 128 + o * 2]     = v;
        g_wt2[k * 128 + o * 2 + 1] = v;
    }
    if (idx < KK * 32) {
        int k = idx >> 5, oc = idx & 31;
        g_owt[idx] = (oc < NOFF) ? ow[oc * KK + k] : 0.f;
    }
}

// ---------------------------------------------------------------------------
// Kernel 1: NCHW -> NHWC transpose of x
// ---------------------------------------------------------------------------
__global__ void k_nhwc(const float* __restrict__ x) {
    __shared__ float tile[32][33];
    const int n = blockIdx.z;
    const int c0 = blockIdx.y * 32, p0 = blockIdx.x * 32;
    const float* xn = x + (size_t)n * CIN * HW;
    float* xtn = g_xt + (size_t)n * HW * CIN;
    const int tx = threadIdx.x & 31, ty = threadIdx.x >> 5;   // 32x8
    #pragma unroll
    for (int i = 0; i < 32; i += 8)
        tile[ty + i][tx] = xn[(size_t)(c0 + ty + i) * HW + p0 + tx];
    __syncthreads();
    #pragma unroll
    for (int i = 0; i < 32; i += 8)
        xtn[(size_t)(p0 + ty + i) * CIN + c0 + tx] = tile[tx][ty + i];
}

// ---------------------------------------------------------------------------
// Kernel 2: offset predictor conv (3x3, pad 1) -> g_raw, bias folded in.
// ---------------------------------------------------------------------------
__global__ void k_offset(const float* __restrict__ x, const float* __restrict__ ob) {
    extern __shared__ float xs[];   // [64][10][20]
    const int tid = threadIdx.x;
    const int wo0 = blockIdx.x * 16, ho0 = blockIdx.y * 8, n = blockIdx.z;
    const float* xn = x + (size_t)n * CIN * HW;

    for (int idx = tid; idx < 64 * 10 * 18; idx += 256) {
        int c = idx / 180;
        int rem = idx - c * 180;
        int r = rem / 18;
        int col = rem - r * 18;
        int gy = ho0 - 1 + r, gx = wo0 - 1 + col;
        float v = 0.f;
        if (gy >= 0 && gy < H && gx >= 0 && gx < W) v = xn[c * HW + gy * W + gx];
        xs[(c * 10 + r) * 20 + col] = v;
    }
    __syncthreads();

    const int g = tid >> 5;
    if (g == 7) return;

    const int lane = tid & 31;
    const int qx = lane & 3, y = lane >> 2;
    const int wx = qx * 4;

    float4 acc[4];
    acc[0] = acc[1] = acc[2] = acc[3] = make_float4(0.f, 0.f, 0.f, 0.f);
    const float4* owt4 = (const float4*)g_owt;   // [KK][8] float4

    for (int c = 0; c < 64; c++) {
        #pragma unroll
        for (int dy = 0; dy < 3; dy++) {
            const float* row = &xs[(c * 10 + y + dy) * 20 + wx];
            float4 rv = *(const float4*)row;
            float2 rv2 = *(const float2*)(row + 4);
            float r0 = rv.x, r1 = rv.y, r2 = rv.z, r3 = rv.w, r4 = rv2.x, r5 = rv2.y;
            int kb = c * 9 + dy * 3;
            float4 w0 = owt4[(kb + 0) * 8 + g];
            float4 w1 = owt4[(kb + 1) * 8 + g];
            float4 w2 = owt4[(kb + 2) * 8 + g];
            fma4(acc[0], r0, w0); fma4(acc[1], r1, w0); fma4(acc[2], r2, w0); fma4(acc[3], r3, w0);
            fma4(acc[0], r1, w1); fma4(acc[1], r2, w1); fma4(acc[2], r3, w1); fma4(acc[3], r4, w1);
            fma4(acc[0], r2, w2); fma4(acc[1], r3, w2); fma4(acc[2], r4, w2); fma4(acc[3], r5, w2);
        }
    }

    const float* af = (const float*)acc;
    const int ho = ho0 + y;
    #pragma unroll
    for (int comp = 0; comp < 4; comp++) {
        int oc = g * 4 + comp;
        if (oc >= NOFF) break;
        float b = ob[oc];
        float4 o4 = make_float4(af[comp] + b, af[4 + comp] + b, af[8 + comp] + b, af[12 + comp] + b);
        *(float4*)&g_raw[(((size_t)n * NOFF + oc) * H + ho) * W + wo0 + wx] = o4;
    }
}

// ---------------------------------------------------------------------------
// Kernel 3: deformable sampling + modulated conv (GEMM), chunked by tap t.
// Tile: 16 wo x 8 ho = 128 px per block, 256 threads, 3 CTAs/SM.
// Per chunk t (9 chunks of 64 k):
//   stage A: corners for 128 px (mask folded)  -> cw_s/ci_s (4 KB)
//   stage B: NHWC coalesced gather -> val_s[c][128 px], swizzle px ^ (c&60)
//   stage C: f32x2 GEMM partial: thread = 4 o x 8 px, 16 FFMA2 per k
// ---------------------------------------------------------------------------
__global__ void __launch_bounds__(256, 3)
k_main(const float* __restrict__ bias, float* __restrict__ out) {
    __shared__ float4 cw_s[128];          // corner weights for current tap
    __shared__ int4   ci_s[128];          // corner flat pixel indices
    __shared__ float  val_s[64 * 128];    // [c][px swizzled]  32 KB

    const int tid = threadIdx.x;
    const int wo0 = blockIdx.x * 16, ho0 = blockIdx.y * 8, n = blockIdx.z;

    const int lane = tid & 31, warp = tid >> 5;
    const int sub = lane >> 4;            // gather: which px of the warp's pair
    const int c4 = (lane & 15) << 2;      // gather: 4 channels per lane
    const float* xtn = g_xt + (size_t)n * (HW * CIN);

    const int og = tid & 15;              // gemm: o = og*4 + {0..3}
    const int pg = tid >> 4;              // gemm: px = pg*8 + {0..7}
    const int pg8 = pg << 3;

    unsigned long long acc[16];           // [o 0..3][px-pair 0..3]
    #pragma unroll
    for (int i = 0; i < 16; i++) acc[i] = 0ULL;

    for (int t = 0; t < 9; t++) {
        // ---- stage A: corners for this tap ----
        if (tid < 128) {
            const int y = tid >> 4, wxl = tid & 15;
            const int ho = ho0 + y, wo = wo0 + wxl;
            size_t rbase = (((size_t)n * NOFF) * H + ho) * W + wo;
            float dyv = g_raw[rbase + (size_t)(2 * t) * HW];
            float dxv = g_raw[rbase + (size_t)(2 * t + 1) * HW];
            float mv  = g_raw[rbase + (size_t)(18 + t) * HW];
            float m = 1.f / (1.f + expf(-mv));
            float py = dyv + (float)(ho - 1 + t / 3);
            float px = dxv + (float)(wo - 1 + t % 3);
            float y0f = floorf(py), x0f = floorf(px);
            float wy1 = py - y0f, wy0 = 1.f - wy1;
            float wx1 = px - x0f, wx0 = 1.f - wx1;
            int y0 = (int)y0f, x0 = (int)x0f;
            int y1 = y0 + 1, x1 = x0 + 1;
            bool vy0 = (y0 >= 0) && (y0 < H), vy1 = (y1 >= 0) && (y1 < H);
            bool vx0 = (x0 >= 0) && (x0 < W), vx1 = (x1 >= 0) && (x1 < W);
            float w00 = (vy0 && vx0) ? wy0 * wx0 * m : 0.f;
            float w01 = (vy0 && vx1) ? wy0 * wx1 * m : 0.f;
            float w10 = (vy1 && vx0) ? wy1 * wx0 * m : 0.f;
            float w11 = (vy1 && vx1) ? wy1 * wx1 * m : 0.f;
            int yc0 = min(max(y0, 0), H - 1), yc1 = min(max(y1, 0), H - 1);
            int xc0 = min(max(x0, 0), W - 1), xc1 = min(max(x1, 0), W - 1);
            cw_s[tid] = make_float4(w00, w01, w10, w11);
            ci_s[tid] = make_int4(yc0 * W + xc0, yc0 * W + xc1, yc1 * W + xc0, yc1 * W + xc1);
        }
        __syncthreads();

        // ---- stage B: coalesced NHWC bilinear gather for this tap ----
        #pragma unroll 2
        for (int it = 0; it < 8; it++) {
            int px = warp * 16 + it * 2 + sub;      // 0..127
            float4 w4 = cw_s[px];
            int4 i4 = ci_s[px];
            float4 g0 = *(const float4*)(xtn + (size_t)i4.x * CIN + c4);
            float4 g1 = *(const float4*)(xtn + (size_t)i4.y * CIN + c4);
            float4 g2 = *(const float4*)(xtn + (size_t)i4.z * CIN + c4);
            float4 g3 = *(const float4*)(xtn + (size_t)i4.w * CIN + c4);
            float4 v;
            v.x = fmaf(w4.w, g3.x, fmaf(w4.z, g2.x, fmaf(w4.y, g1.x, w4.x * g0.x)));
            v.y = fmaf(w4.w, g3.y, fmaf(w4.z, g2.y, fmaf(w4.y, g1.y, w4.x * g0.y)));
            v.z = fmaf(w4.w, g3.z, fmaf(w4.z, g2.z, fmaf(w4.y, g1.z, w4.x * g0.z)));
            v.w = fmaf(w4.w, g3.w, fmaf(w4.z, g2.w, fmaf(w4.y, g1.w, w4.x * g0.w)));
            int spx = px ^ c4;                      // swizzle: c&60 == c4 for this group
            float* vp = val_s + c4 * 128 + spx;
            vp[0]   = v.x;
            vp[128] = v.y;
            vp[256] = v.z;
            vp[384] = v.w;
        }
        __syncthreads();

        // ---- stage C: partial f32x2 GEMM over this chunk's 64 k ----
        const ulonglong2* wp = (const ulonglong2*)g_wt2 + (size_t)(t * 64) * 32 + og * 2;
        #pragma unroll 4
        for (int c = 0; c < 64; c++) {
            ulonglong2 wv0 = __ldg(wp);          // {w_o0,w_o0},{w_o1,w_o1}
            ulonglong2 wv1 = __ldg(wp + 1);      // {w_o2,w_o2},{w_o3,w_o3}
            int b0 = pg8 ^ (c & 60);
            const ulonglong2* v0p = (const ulonglong2*)(val_s + c * 128 + b0);
            const ulonglong2* v1p = (const ulonglong2*)(val_s + c * 128 + (b0 ^ 4));
            ulonglong2 va = *v0p;                // px pairs (0,1),(2,3)
            ulonglong2 vb = *v1p;                // px pairs (4,5),(6,7)
            FMA2(acc[0],  wv0.x, va.x); FMA2(acc[1],  wv0.x, va.y);
            FMA2(acc[2],  wv0.x, vb.x); FMA2(acc[3],  wv0.x, vb.y);
            FMA2(acc[4],  wv0.y, va.x); FMA2(acc[5],  wv0.y, va.y);
            FMA2(acc[6],  wv0.y, vb.x); FMA2(acc[7],  wv0.y, vb.y);
            FMA2(acc[8],  wv1.x, va.x); FMA2(acc[9],  wv1.x, va.y);
            FMA2(acc[10], wv1.x, vb.x); FMA2(acc[11], wv1.x, vb.y);
            FMA2(acc[12], wv1.y, va.x); FMA2(acc[13], wv1.y, va.y);
            FMA2(acc[14], wv1.y, vb.x); FMA2(acc[15], wv1.y, vb.y);
            wp += 32;                            // next k row (64 ull)
        }
        __syncthreads();
    }

    // ---- epilogue: unpack, add bias, write 4 o x 8 px ----
    const int ho = ho0 + (pg >> 1);
    const int wo = wo0 + (pg & 1) * 8;
    #pragma unroll
    for (int j = 0; j < 4; j++) {
        int o = og * 4 + j;
        float b = bias[o];
        float4 r0, r1;
        asm("mov.b64 {%0,%1}, %2;" : "=f"(r0.x), "=f"(r0.y) : "l"(acc[j * 4 + 0]));
        asm("mov.b64 {%0,%1}, %2;" : "=f"(r0.z), "=f"(r0.w) : "l"(acc[j * 4 + 1]));
        asm("mov.b64 {%0,%1}, %2;" : "=f"(r1.x), "=f"(r1.y) : "l"(acc[j * 4 + 2]));
        asm("mov.b64 {%0,%1}, %2;" : "=f"(r1.z), "=f"(r1.w) : "l"(acc[j * 4 + 3]));
        r0.x += b; r0.y += b; r0.z += b; r0.w += b;
        r1.x += b; r1.y += b; r1.z += b; r1.w += b;
        float* op = &out[(((size_t)n * OUTC + o) * H + ho) * W + wo];
        *(float4*)op = r0;
        *(float4*)(op + 4) = r1;
    }
}

// ---------------------------------------------------------------------------
extern "C" void kernel_launch(void* const* d_in, const int* in_sizes, int n_in,
                              void* d_out, int out_size) {
    (void)in_sizes; (void)n_in; (void)out_size;
    const float* x        = (const float*)d_in[0];
    const float* weight   = (const float*)d_in[1];
    const float* bias     = (const float*)d_in[2];
    const float* offset_w = (const float*)d_in[3];
    const float* offset_b = (const float*)d_in[4];
    float* out = (float*)d_out;

    cudaFuncSetAttribute(k_offset, cudaFuncAttributeMaxDynamicSharedMemorySize, 51200);

    k_transpose<<<144, 256>>>(weight, offset_w);
    k_nhwc<<<dim3(392, 2, 8), 256>>>(x);
    k_offset<<<dim3(7, 14, 8), 256, 51200>>>(x, offset_b);
    k_main<<<dim3(7, 14, 8), 256>>>(bias, out);
}

// round 4
// speedup vs baseline: 3.3043x; 1.2826x over previous
#include <cuda_runtime.h>
#include <math.h>

// Problem constants (fixed shapes from reference)
#define H 112
#define W 112
#define HW 12544
#define CIN 64
#define OUTC 64
#define NB 8
#define NOFF 27          // 3*K*K
#define KK 576           // CIN * 9

// Scratch (static __device__ — no runtime allocation)
__device__ float g_raw[NB * NOFF * HW];                 // offset-conv output [N][27][H][W]
__device__ __align__(16) float g_xt[NB * HW * CIN];     // x in NHWC [N][H][W][C]
__device__ __align__(16) float g_wtn[KK * 64];          // weights non-dup: [(t*64+c)][o]
__device__ __align__(16) float g_owt[KK * 32];          // offset_w transposed [k][oc], k=c*9+t

#define FMA2(d, a, b) asm("fma.rn.f32x2 %0, %1, %2, %3;" : "=l"(d) : "l"(a), "l"(b), "l"(d))
#define DUP2(d, s)    asm("mov.b64 %0, {%1, %1};" : "=l"(d) : "f"(s))
#define UNPK(lo, hi, s) asm("mov.b64 {%0, %1}, %2;" : "=f"(lo), "=f"(hi) : "l"(s))

// ---------------------------------------------------------------------------
// Kernel 0: weight layouts.
//  g_wtn[(t*64+c)*64 + o]  = weight[o][c][t]
//  g_owt[(c*9+t)*32 + oc]  = offset_w[oc][c][t] (padded oc->32)
// ---------------------------------------------------------------------------
__global__ void k_transpose(const float* __restrict__ w, const float* __restrict__ ow) {
    int idx = blockIdx.x * 256 + threadIdx.x;
    if (idx < KK * 64) {
        int k = idx >> 6, o = idx & 63;        // k' = t*64 + c
        int t = k >> 6, c = k & 63;
        g_wtn[idx] = w[o * KK + c * 9 + t];
    }
    if (idx < KK * 32) {
        int k = idx >> 5, oc = idx & 31;
        g_owt[idx] = (oc < NOFF) ? ow[oc * KK + k] : 0.f;
    }
}

// ---------------------------------------------------------------------------
// Kernel 1: NCHW -> NHWC transpose of x
// ---------------------------------------------------------------------------
__global__ void k_nhwc(const float* __restrict__ x) {
    __shared__ float tile[32][33];
    const int n = blockIdx.z;
    const int c0 = blockIdx.y * 32, p0 = blockIdx.x * 32;
    const float* xn = x + (size_t)n * CIN * HW;
    float* xtn = g_xt + (size_t)n * HW * CIN;
    const int tx = threadIdx.x & 31, ty = threadIdx.x >> 5;   // 32x8
    #pragma unroll
    for (int i = 0; i < 32; i += 8)
        tile[ty + i][tx] = xn[(size_t)(c0 + ty + i) * HW + p0 + tx];
    __syncthreads();
    #pragma unroll
    for (int i = 0; i < 32; i += 8)
        xtn[(size_t)(p0 + ty + i) * CIN + c0 + tx] = tile[tx][ty + i];
}

// ---------------------------------------------------------------------------
// Kernel 2: offset predictor conv (3x3, pad 1) -> g_raw, bias folded in.
// f32x2 version: acc packs oc-pairs; weights are natural pairs in g_owt;
// scalar input r duplicated {r,r} via mov.b64 (ALU pipe).
// ---------------------------------------------------------------------------
__global__ void k_offset(const float* __restrict__ x, const float* __restrict__ ob) {
    extern __shared__ float xs[];   // [64][10][20]
    const int tid = threadIdx.x;
    const int wo0 = blockIdx.x * 16, ho0 = blockIdx.y * 8, n = blockIdx.z;
    const float* xn = x + (size_t)n * CIN * HW;

    for (int idx = tid; idx < 64 * 10 * 18; idx += 256) {
        int c = idx / 180;
        int rem = idx - c * 180;
        int r = rem / 18;
        int col = rem - r * 18;
        int gy = ho0 - 1 + r, gx = wo0 - 1 + col;
        float v = 0.f;
        if (gy >= 0 && gy < H && gx >= 0 && gx < W) v = xn[c * HW + gy * W + gx];
        xs[(c * 10 + r) * 20 + col] = v;
    }
    __syncthreads();

    const int g = tid >> 5;
    if (g == 7) return;

    const int lane = tid & 31;
    const int qx = lane & 3, y = lane >> 2;
    const int wx = qx * 4;

    unsigned long long A[2][4];     // [oc-pair p][px j]
    #pragma unroll
    for (int p = 0; p < 2; p++)
        #pragma unroll
        for (int j = 0; j < 4; j++) A[p][j] = 0ULL;

    const ulonglong2* ow2 = (const ulonglong2*)g_owt;   // row = 8 x ulonglong2

    for (int c = 0; c < 64; c++) {
        #pragma unroll
        for (int dy = 0; dy < 3; dy++) {
            const float* row = &xs[(c * 10 + y + dy) * 20 + wx];
            float4 rv = *(const float4*)row;
            float2 rv2 = *(const float2*)(row + 4);
            unsigned long long R[6];
            DUP2(R[0], rv.x); DUP2(R[1], rv.y); DUP2(R[2], rv.z);
            DUP2(R[3], rv.w); DUP2(R[4], rv2.x); DUP2(R[5], rv2.y);
            int kb = c * 9 + dy * 3;
            ulonglong2 W0 = ow2[(kb + 0) * 8 + g];   // {oc0,oc1},{oc2,oc3}
            ulonglong2 W1 = ow2[(kb + 1) * 8 + g];
            ulonglong2 W2 = ow2[(kb + 2) * 8 + g];
            #pragma unroll
            for (int j = 0; j < 4; j++) {
                FMA2(A[0][j], W0.x, R[j]);     FMA2(A[1][j], W0.y, R[j]);
                FMA2(A[0][j], W1.x, R[j + 1]); FMA2(A[1][j], W1.y, R[j + 1]);
                FMA2(A[0][j], W2.x, R[j + 2]); FMA2(A[1][j], W2.y, R[j + 2]);
            }
        }
    }

    // unpack: up[p][j] = {oc=g*4+2p (lo), oc+1 (hi)} at px j
    float2 up[2][4];
    #pragma unroll
    for (int p = 0; p < 2; p++)
        #pragma unroll
        for (int j = 0; j < 4; j++) UNPK(up[p][j].x, up[p][j].y, A[p][j]);

    const int ho = ho0 + y;
    #pragma unroll
    for (int comp = 0; comp < 4; comp++) {
        int oc = g * 4 + comp;
        if (oc >= NOFF) break;
        int p = comp >> 1, e = comp & 1;
        float b = ob[oc];
        float4 o4;
        o4.x = (e ? up[p][0].y : up[p][0].x) + b;
        o4.y = (e ? up[p][1].y : up[p][1].x) + b;
        o4.z = (e ? up[p][2].y : up[p][2].x) + b;
        o4.w = (e ? up[p][3].y : up[p][3].x) + b;
        *(float4*)&g_raw[(((size_t)n * NOFF + oc) * H + ho) * W + wo0 + wx] = o4;
    }
}

// ---------------------------------------------------------------------------
// Kernel 3: deformable sampling + modulated conv (GEMM), chunked by tap t.
// Tile: 16 wo x 8 ho = 128 px, 256 threads (8 warps), 3 CTAs/SM.
// Per chunk t (9 chunks of 64 k=c):
//   stage A: corners for 128 px (mask folded); also stage weights w_s (16 KB)
//   stage B: NHWC coalesced gather -> val_s[c][128 px], swizzle px ^ (c&60)
//   stage C: warp = 16 o x 64 px (lane = 2 px). Per k: 4x LDS.128 broadcast
//            weights (non-dup) + 1x LDS.64 vals + 2 mov dup + 16 FFMA2.
// ---------------------------------------------------------------------------
__global__ void __launch_bounds__(256, 3)
k_main(const float* __restrict__ bias, float* __restrict__ out) {
    extern __shared__ unsigned char sm[];
    float4* cw_s = (float4*)sm;                    // [128] corner weights   (2 KB)
    int4*   ci_s = (int4*)(sm + 2048);             // [128] corner indices   (2 KB)
    float*  val_s = (float*)(sm + 4096);           // [64][128] swizzled     (32 KB)
    float*  w_s   = (float*)(sm + 36864);          // [64 c][64 o]           (16 KB)

    const int tid = threadIdx.x;
    const int wo0 = blockIdx.x * 16, ho0 = blockIdx.y * 8, n = blockIdx.z;

    const int lane = tid & 31, warp = tid >> 5;
    // gather mapping
    const int sub = lane >> 4;
    const int c4 = (lane & 15) << 2;
    const float* xtn = g_xt + (size_t)n * (HW * CIN);
    // gemm mapping: warp covers o [og*16, og*16+16) x px [pxg*64, pxg*64+64)
    const int og = warp >> 1;
    const int pxg = warp & 1;
    const int pxb = pxg * 64 + lane * 2;           // 2 adjacent px per lane

    unsigned long long acc[8][2];                  // [o-pair][px 0/1]
    #pragma unroll
    for (int i = 0; i < 8; i++) { acc[i][0] = 0ULL; acc[i][1] = 0ULL; }

    for (int t = 0; t < 9; t++) {
        // ---- stage A: weights -> smem, corners for this tap ----
        {
            const float4* wsrc = (const float4*)(g_wtn + t * 4096);
            float4* wdst = (float4*)w_s;
            #pragma unroll
            for (int i = 0; i < 4; i++) wdst[tid + i * 256] = wsrc[tid + i * 256];
        }
        if (tid < 128) {
            const int y = tid >> 4, wxl = tid & 15;
            const int ho = ho0 + y, wo = wo0 + wxl;
            size_t rbase = (((size_t)n * NOFF) * H + ho) * W + wo;
            float dyv = g_raw[rbase + (size_t)(2 * t) * HW];
            float dxv = g_raw[rbase + (size_t)(2 * t + 1) * HW];
            float mv  = g_raw[rbase + (size_t)(18 + t) * HW];
            float m = 1.f / (1.f + expf(-mv));
            float py = dyv + (float)(ho - 1 + t / 3);
            float px = dxv + (float)(wo - 1 + t % 3);
            float y0f = floorf(py), x0f = floorf(px);
            float wy1 = py - y0f, wy0 = 1.f - wy1;
            float wx1 = px - x0f, wx0 = 1.f - wx1;
            int y0 = (int)y0f, x0 = (int)x0f;
            int y1 = y0 + 1, x1 = x0 + 1;
            bool vy0 = (y0 >= 0) && (y0 < H), vy1 = (y1 >= 0) && (y1 < H);
            bool vx0 = (x0 >= 0) && (x0 < W), vx1 = (x1 >= 0) && (x1 < W);
            float w00 = (vy0 && vx0) ? wy0 * wx0 * m : 0.f;
            float w01 = (vy0 && vx1) ? wy0 * wx1 * m : 0.f;
            float w10 = (vy1 && vx0) ? wy1 * wx0 * m : 0.f;
            float w11 = (vy1 && vx1) ? wy1 * wx1 * m : 0.f;
            int yc0 = min(max(y0, 0), H - 1), yc1 = min(max(y1, 0), H - 1);
            int xc0 = min(max(x0, 0), W - 1), xc1 = min(max(x1, 0), W - 1);
            cw_s[tid] = make_float4(w00, w01, w10, w11);
            ci_s[tid] = make_int4(yc0 * W + xc0, yc0 * W + xc1, yc1 * W + xc0, yc1 * W + xc1);
        }
        __syncthreads();

        // ---- stage B: coalesced NHWC bilinear gather for this tap ----
        #pragma unroll 2
        for (int it = 0; it < 8; it++) {
            int px = warp * 16 + it * 2 + sub;      // 0..127
            float4 w4 = cw_s[px];
            int4 i4 = ci_s[px];
            float4 g0 = *(const float4*)(xtn + (size_t)i4.x * CIN + c4);
            float4 g1 = *(const float4*)(xtn + (size_t)i4.y * CIN + c4);
            float4 g2 = *(const float4*)(xtn + (size_t)i4.z * CIN + c4);
            float4 g3 = *(const float4*)(xtn + (size_t)i4.w * CIN + c4);
            float4 v;
            v.x = fmaf(w4.w, g3.x, fmaf(w4.z, g2.x, fmaf(w4.y, g1.x, w4.x * g0.x)));
            v.y = fmaf(w4.w, g3.y, fmaf(w4.z, g2.y, fmaf(w4.y, g1.y, w4.x * g0.y)));
            v.z = fmaf(w4.w, g3.z, fmaf(w4.z, g2.z, fmaf(w4.y, g1.z, w4.x * g0.z)));
            v.w = fmaf(w4.w, g3.w, fmaf(w4.z, g2.w, fmaf(w4.y, g1.w, w4.x * g0.w)));
            int spx = px ^ c4;                      // swizzle (c&60 == c4 for rows c4..c4+3)
            float* vp = val_s + c4 * 128 + spx;
            vp[0]   = v.x;
            vp[128] = v.y;
            vp[256] = v.z;
            vp[384] = v.w;
        }
        __syncthreads();

        // ---- stage C: partial f32x2 GEMM over this chunk's 64 k ----
        {
            const ulonglong2* ws2 = (const ulonglong2*)w_s;   // row = 16 ull2
            #pragma unroll 4
            for (int c = 0; c < 64; c++) {
                float2 vv = *(const float2*)&val_s[c * 128 + (pxb ^ (c & 60))];
                unsigned long long va, vb;
                DUP2(va, vv.x);
                DUP2(vb, vv.y);
                ulonglong2 w01 = ws2[c * 16 + og * 4 + 0];   // {o0,o1},{o2,o3}
                ulonglong2 w23 = ws2[c * 16 + og * 4 + 1];
                ulonglong2 w45 = ws2[c * 16 + og * 4 + 2];
                ulonglong2 w67 = ws2[c * 16 + og * 4 + 3];
                FMA2(acc[0][0], w01.x, va); FMA2(acc[0][1], w01.x, vb);
                FMA2(acc[1][0], w01.y, va); FMA2(acc[1][1], w01.y, vb);
                FMA2(acc[2][0], w23.x, va); FMA2(acc[2][1], w23.x, vb);
                FMA2(acc[3][0], w23.y, va); FMA2(acc[3][1], w23.y, vb);
                FMA2(acc[4][0], w45.x, va); FMA2(acc[4][1], w45.x, vb);
                FMA2(acc[5][0], w45.y, va); FMA2(acc[5][1], w45.y, vb);
                FMA2(acc[6][0], w67.x, va); FMA2(acc[6][1], w67.x, vb);
                FMA2(acc[7][0], w67.y, va); FMA2(acc[7][1], w67.y, vb);
            }
        }
        __syncthreads();
    }

    // ---- epilogue: unpack, add bias, write 16 o x 2 px per lane ----
    const int ho = ho0 + (pxb >> 4);
    const int wo = wo0 + (pxb & 15);
    #pragma unroll
    for (int op = 0; op < 8; op++) {
        float e0, o0, e1, o1;
        UNPK(e0, o0, acc[op][0]);    // px0: {o_even, o_odd}
        UNPK(e1, o1, acc[op][1]);    // px1
        int oe = og * 16 + op * 2;
        float be = bias[oe], bo = bias[oe + 1];
        float2 re = make_float2(e0 + be, e1 + be);
        float2 ro = make_float2(o0 + bo, o1 + bo);
        *(float2*)&out[(((size_t)n * OUTC + oe) * H + ho) * W + wo] = re;
        *(float2*)&out[(((size_t)n * OUTC + oe + 1) * H + ho) * W + wo] = ro;
    }
}

// ---------------------------------------------------------------------------
extern "C" void kernel_launch(void* const* d_in, const int* in_sizes, int n_in,
                              void* d_out, int out_size) {
    (void)in_sizes; (void)n_in; (void)out_size;
    const float* x        = (const float*)d_in[0];
    const float* weight   = (const float*)d_in[1];
    const float* bias     = (const float*)d_in[2];
    const float* offset_w = (const float*)d_in[3];
    const float* offset_b = (const float*)d_in[4];
    float* out = (float*)d_out;

    cudaFuncSetAttribute(k_offset, cudaFuncAttributeMaxDynamicSharedMemorySize, 51200);
    cudaFuncSetAttribute(k_main,   cudaFuncAttributeMaxDynamicSharedMemorySize, 53248);

    k_transpose<<<144, 256>>>(weight, offset_w);
    k_nhwc<<<dim3(392, 2, 8), 256>>>(x);
    k_offset<<<dim3(7, 14, 8), 256, 51200>>>(x, offset_b);
    k_main<<<dim3(7, 14, 8), 256, 53248>>>(bias, out);
}

// round 6
// speedup vs baseline: 4.6410x; 1.4045x over previous
#include <cuda_runtime.h>
#include <math.h>
#include <stdint.h>

// Problem constants (fixed shapes from reference)
#define H 112
#define W 112
#define HW 12544
#define CIN 64
#define OUTC 64
#define NB 8
#define NOFF 27          // 3*K*K
#define KK 576           // CIN * 9

// Scratch (static __device__ — no runtime allocation)
__device__ float g_raw[NB * NOFF * HW];                 // offset-conv output [N][27][H][W]
__device__ __align__(16) float g_xt[NB * HW * CIN];     // x in NHWC [N][H][W][C]
__device__ __align__(16) float g_wtt[9 * 64 * 64];      // weights per-tap [t][o][c], tf32 bits
__device__ __align__(16) float g_owt[KK * 32];          // offset_w transposed [k][oc], k=c*9+t

#define FMA2(d, a, b) asm("fma.rn.f32x2 %0, %1, %2, %3;" : "=l"(d) : "l"(a), "l"(b), "l"(d))
#define DUP2(d, s)    asm("mov.b64 %0, {%1, %1};" : "=l"(d) : "f"(s))
#define UNPK(lo, hi, s) asm("mov.b64 {%0, %1}, %2;" : "=f"(lo), "=f"(hi) : "l"(s))
#define CVT_TF32(u, f) asm("cvt.rna.tf32.f32 %0, %1;" : "=r"(u) : "f"(f))

#define MMA_TF32(d, a0, a1, a2, a3, b0, b1)                                   \
    asm volatile("mma.sync.aligned.m16n8k8.row.col.f32.tf32.tf32.f32 "        \
        "{%0,%1,%2,%3}, {%4,%5,%6,%7}, {%8,%9}, {%0,%1,%2,%3};"               \
        : "+f"((d)[0]), "+f"((d)[1]), "+f"((d)[2]), "+f"((d)[3])              \
        : "r"(a0), "r"(a1), "r"(a2), "r"(a3), "r"(b0), "r"(b1))

// ---------------------------------------------------------------------------
// Kernel 0: weight prep.
//  g_wtt[t][o][c] = tf32(weight[o][c][t])
//  g_owt[(c*9+t)*32 + oc] = offset_w[oc][c][t] (padded oc->32)
// ---------------------------------------------------------------------------
__global__ void k_wprep(const float* __restrict__ w, const float* __restrict__ ow) {
    int idx = blockIdx.x * 256 + threadIdx.x;     // 0..36863
    if (idx < KK * 32) {
        int k = idx >> 5, oc = idx & 31;
        g_owt[idx] = (oc < NOFF) ? ow[oc * KK + k] : 0.f;
    }
    {
        int t = idx >> 12, o = (idx >> 6) & 63, c = idx & 63;
        float v = w[o * KK + c * 9 + t];
        uint32_t u; CVT_TF32(u, v);
        ((uint32_t*)g_wtt)[idx] = u;
    }
}

// ---------------------------------------------------------------------------
// Kernel 1: NCHW -> NHWC transpose of x
// ---------------------------------------------------------------------------
__global__ void k_nhwc(const float* __restrict__ x) {
    __shared__ float tile[32][33];
    const int n = blockIdx.z;
    const int c0 = blockIdx.y * 32, p0 = blockIdx.x * 32;
    const float* xn = x + (size_t)n * CIN * HW;
    float* xtn = g_xt + (size_t)n * HW * CIN;
    const int tx = threadIdx.x & 31, ty = threadIdx.x >> 5;   // 32x8
    #pragma unroll
    for (int i = 0; i < 32; i += 8)
        tile[ty + i][tx] = xn[(size_t)(c0 + ty + i) * HW + p0 + tx];
    __syncthreads();
    #pragma unroll
    for (int i = 0; i < 32; i += 8)
        xtn[(size_t)(p0 + ty + i) * CIN + c0 + tx] = tile[tx][ty + i];
}

// ---------------------------------------------------------------------------
// Kernel 2: offset predictor conv (3x3, pad 1) -> g_raw, bias folded (f32x2).
// ---------------------------------------------------------------------------
__global__ void k_offset(const float* __restrict__ x, const float* __restrict__ ob) {
    extern __shared__ float xs[];   // [64][10][20]
    const int tid = threadIdx.x;
    const int wo0 = blockIdx.x * 16, ho0 = blockIdx.y * 8, n = blockIdx.z;
    const float* xn = x + (size_t)n * CIN * HW;

    for (int idx = tid; idx < 64 * 10 * 18; idx += 256) {
        int c = idx / 180;
        int rem = idx - c * 180;
        int r = rem / 18;
        int col = rem - r * 18;
        int gy = ho0 - 1 + r, gx = wo0 - 1 + col;
        float v = 0.f;
        if (gy >= 0 && gy < H && gx >= 0 && gx < W) v = xn[c * HW + gy * W + gx];
        xs[(c * 10 + r) * 20 + col] = v;
    }
    __syncthreads();

    const int g = tid >> 5;
    if (g == 7) return;

    const int lane = tid & 31;
    const int qx = lane & 3, y = lane >> 2;
    const int wx = qx * 4;

    unsigned long long A[2][4];
    #pragma unroll
    for (int p = 0; p < 2; p++)
        #pragma unroll
        for (int j = 0; j < 4; j++) A[p][j] = 0ULL;

    const ulonglong2* ow2 = (const ulonglong2*)g_owt;

    for (int c = 0; c < 64; c++) {
        #pragma unroll
        for (int dy = 0; dy < 3; dy++) {
            const float* row = &xs[(c * 10 + y + dy) * 20 + wx];
            float4 rv = *(const float4*)row;
            float2 rv2 = *(const float2*)(row + 4);
            unsigned long long R[6];
            DUP2(R[0], rv.x); DUP2(R[1], rv.y); DUP2(R[2], rv.z);
            DUP2(R[3], rv.w); DUP2(R[4], rv2.x); DUP2(R[5], rv2.y);
            int kb = c * 9 + dy * 3;
            ulonglong2 W0 = ow2[(kb + 0) * 8 + g];
            ulonglong2 W1 = ow2[(kb + 1) * 8 + g];
            ulonglong2 W2 = ow2[(kb + 2) * 8 + g];
            #pragma unroll
            for (int j = 0; j < 4; j++) {
                FMA2(A[0][j], W0.x, R[j]);     FMA2(A[1][j], W0.y, R[j]);
                FMA2(A[0][j], W1.x, R[j + 1]); FMA2(A[1][j], W1.y, R[j + 1]);
                FMA2(A[0][j], W2.x, R[j + 2]); FMA2(A[1][j], W2.y, R[j + 2]);
            }
        }
    }

    float2 up[2][4];
    #pragma unroll
    for (int p = 0; p < 2; p++)
        #pragma unroll
        for (int j = 0; j < 4; j++) UNPK(up[p][j].x, up[p][j].y, A[p][j]);

    const int ho = ho0 + y;
    #pragma unroll
    for (int comp = 0; comp < 4; comp++) {
        int oc = g * 4 + comp;
        if (oc >= NOFF) break;
        int p = comp >> 1, e = comp & 1;
        float b = ob[oc];
        float4 o4;
        o4.x = (e ? up[p][0].y : up[p][0].x) + b;
        o4.y = (e ? up[p][1].y : up[p][1].x) + b;
        o4.z = (e ? up[p][2].y : up[p][2].x) + b;
        o4.w = (e ? up[p][3].y : up[p][3].x) + b;
        *(float4*)&g_raw[(((size_t)n * NOFF + oc) * H + ho) * W + wo0 + wx] = o4;
    }
}

// ---------------------------------------------------------------------------
// Kernel 3: deformable sampling + tf32 mma.sync GEMM, chunked by tap t.
// Tile: 16 wo x 8 ho = 128 px, 256 threads (8 warps), 2 CTAs/SM.
// SMEM: val_s [128 px][68]  (34816 B, pad-68 -> bank = 4*row+col)
//       w_s   [64 o][68]    (17408 B)
//       cw/ci corners, bias
// Per tap t (9 chunks of K=64):
//   A: copy weights [o][c]->w_s (padded); corners for 128 px (mask folded)
//   B: NHWC coalesced gather -> val_s (tf32), one STS.128 per lane
//   C: warp = 16 px x 64 o: 8 k-steps x (4 A-LDS + 8x(2 B-LDS + mma))
// Epilogue: per-thread D frags + bias -> NCHW out.
// ---------------------------------------------------------------------------
__global__ void __launch_bounds__(256, 2)
k_main(const float* __restrict__ bias, float* __restrict__ out) {
    extern __shared__ unsigned char sm[];
    float*  val_s = (float*)sm;                  // [128][68]
    float*  w_s   = (float*)(sm + 34816);        // [64][68]
    float4* cw_s  = (float4*)(sm + 52224);       // [128]
    int4*   ci_s  = (int4*)(sm + 54272);         // [128]
    float*  bs    = (float*)(sm + 56320);        // [64]

    const int tid = threadIdx.x;
    const int wo0 = blockIdx.x * 16, ho0 = blockIdx.y * 8, n = blockIdx.z;
    const int lane = tid & 31, warp = tid >> 5;

    if (tid < 64) bs[tid] = bias[tid];

    // gather mapping
    const int sub = lane >> 4;
    const int c4 = (lane & 15) << 2;
    const float* xtn = g_xt + (size_t)n * (HW * CIN);

    // mma mapping
    const int g = lane >> 2, ti = lane & 3;
    const int px0 = warp * 16;

    float acc[8][4];
    #pragma unroll
    for (int j = 0; j < 8; j++)
        #pragma unroll
        for (int i = 0; i < 4; i++) acc[j][i] = 0.f;

    for (int t = 0; t < 9; t++) {
        // ---- stage A: weights -> w_s (padded 68); corners ----
        {
            const float4* wsrc = (const float4*)(g_wtt + t * 4096);
            const int o = tid >> 2, q = (tid & 3) * 4;   // q: float4 index within row
            #pragma unroll
            for (int i = 0; i < 4; i++) {                // wait: 4 float4 per thread
                ;
            }
            // each thread copies 4 float4 = 16 floats: row o, cols [q*4 .. ) pattern
            #pragma unroll
            for (int i = 0; i < 4; i++) {
                float4 v = wsrc[o * 16 + q + i];
                *(float4*)(w_s + o * 68 + (q + i) * 4) = v;
            }
        }
        if (tid < 128) {
            const int y = tid >> 4, wxl = tid & 15;
            const int ho = ho0 + y, wo = wo0 + wxl;
            size_t rbase = (((size_t)n * NOFF) * H + ho) * W + wo;
            float dyv = g_raw[rbase + (size_t)(2 * t) * HW];
            float dxv = g_raw[rbase + (size_t)(2 * t + 1) * HW];
            float mv  = g_raw[rbase + (size_t)(18 + t) * HW];
            float m = 1.f / (1.f + expf(-mv));
            float py = dyv + (float)(ho - 1 + t / 3);
            float px = dxv + (float)(wo - 1 + t % 3);
            float y0f = floorf(py), x0f = floorf(px);
            float wy1 = py - y0f, wy0 = 1.f - wy1;
            float wx1 = px - x0f, wx0 = 1.f - wx1;
            int y0 = (int)y0f, x0 = (int)x0f;
            int y1 = y0 + 1, x1 = x0 + 1;
            bool vy0 = (y0 >= 0) && (y0 < H), vy1 = (y1 >= 0) && (y1 < H);
            bool vx0 = (x0 >= 0) && (x0 < W), vx1 = (x1 >= 0) && (x1 < W);
            float w00 = (vy0 && vx0) ? wy0 * wx0 * m : 0.f;
            float w01 = (vy0 && vx1) ? wy0 * wx1 * m : 0.f;
            float w10 = (vy1 && vx0) ? wy1 * wx0 * m : 0.f;
            float w11 = (vy1 && vx1) ? wy1 * wx1 * m : 0.f;
            int yc0 = min(max(y0, 0), H - 1), yc1 = min(max(y1, 0), H - 1);
            int xc0 = min(max(x0, 0), W - 1), xc1 = min(max(x1, 0), W - 1);
            cw_s[tid] = make_float4(w00, w01, w10, w11);
            ci_s[tid] = make_int4(yc0 * W + xc0, yc0 * W + xc1, yc1 * W + xc0, yc1 * W + xc1);
        }
        __syncthreads();

        // ---- stage B: coalesced NHWC bilinear gather -> val_s (tf32) ----
        #pragma unroll 2
        for (int it = 0; it < 8; it++) {
            int px = warp * 16 + it * 2 + sub;      // 0..127
            float4 w4 = cw_s[px];
            int4 i4 = ci_s[px];
            float4 g0 = *(const float4*)(xtn + (size_t)i4.x * CIN + c4);
            float4 g1 = *(const float4*)(xtn + (size_t)i4.y * CIN + c4);
            float4 g2 = *(const float4*)(xtn + (size_t)i4.z * CIN + c4);
            float4 g3 = *(const float4*)(xtn + (size_t)i4.w * CIN + c4);
            float4 v;
            v.x = fmaf(w4.w, g3.x, fmaf(w4.z, g2.x, fmaf(w4.y, g1.x, w4.x * g0.x)));
            v.y = fmaf(w4.w, g3.y, fmaf(w4.z, g2.y, fmaf(w4.y, g1.y, w4.x * g0.y)));
            v.z = fmaf(w4.w, g3.z, fmaf(w4.z, g2.z, fmaf(w4.y, g1.z, w4.x * g0.z)));
            v.w = fmaf(w4.w, g3.w, fmaf(w4.z, g2.w, fmaf(w4.y, g1.w, w4.x * g0.w)));
            uint4 u;
            CVT_TF32(u.x, v.x); CVT_TF32(u.y, v.y);
            CVT_TF32(u.z, v.z); CVT_TF32(u.w, v.w);
            *(uint4*)(val_s + px * 68 + c4) = u;
        }
        __syncthreads();

        // ---- stage C: mma.sync tf32 over this chunk's K=64 ----
        {
            const uint32_t* vsu = (const uint32_t*)val_s;
            const uint32_t* wsu = (const uint32_t*)w_s;
            #pragma unroll
            for (int s = 0; s < 8; s++) {
                const int c0 = s * 8;
                const uint32_t* ap = vsu + (px0 + g) * 68 + c0 + ti;
                uint32_t a0 = ap[0];
                uint32_t a2 = ap[4];
                uint32_t a1 = ap[8 * 68];
                uint32_t a3 = ap[8 * 68 + 4];
                #pragma unroll
                for (int j = 0; j < 8; j++) {
                    const uint32_t* bp = wsu + (j * 8 + g) * 68 + c0 + ti;
                    uint32_t b0 = bp[0];
                    uint32_t b1 = bp[4];
                    MMA_TF32(acc[j], a0, a1, a2, a3, b0, b1);
                }
            }
        }
        __syncthreads();
    }

    // ---- epilogue: D frags + bias -> out (NCHW) ----
    // thread owns px rows {px0+g, px0+8+g}, o = 8j + 2*ti + {0,1}
    const int ho = ho0 + warp;                 // px0 = 16*warp -> y = warp
    float* ob = out + (((size_t)n * OUTC) * H + ho) * W + wo0;
    #pragma unroll
    for (int j = 0; j < 8; j++) {
        int o0 = 8 * j + 2 * ti;
        float b0v = bs[o0], b1v = bs[o0 + 1];
        ob[(size_t)o0 * HW + g]            = acc[j][0] + b0v;
        ob[(size_t)(o0 + 1) * HW + g]      = acc[j][1] + b1v;
        ob[(size_t)o0 * HW + g + 8]        = acc[j][2] + b0v;
        ob[(size_t)(o0 + 1) * HW + g + 8]  = acc[j][3] + b1v;
    }
}

// ---------------------------------------------------------------------------
extern "C" void kernel_launch(void* const* d_in, const int* in_sizes, int n_in,
                              void* d_out, int out_size) {
    (void)in_sizes; (void)n_in; (void)out_size;
    const float* x        = (const float*)d_in[0];
    const float* weight   = (const float*)d_in[1];
    const float* bias     = (const float*)d_in[2];
    const float* offset_w = (const float*)d_in[3];
    const float* offset_b = (const float*)d_in[4];
    float* out = (float*)d_out;

    cudaFuncSetAttribute(k_offset, cudaFuncAttributeMaxDynamicSharedMemorySize, 51200);
    cudaFuncSetAttribute(k_main,   cudaFuncAttributeMaxDynamicSharedMemorySize, 56576);

    k_wprep<<<144, 256>>>(weight, offset_w);
    k_nhwc<<<dim3(392, 2, 8), 256>>>(x);
    k_offset<<<dim3(7, 14, 8), 256, 51200>>>(x, offset_b);
    k_main<<<dim3(7, 14, 8), 256, 56576>>>(bias, out);
}

// round 7
// speedup vs baseline: 7.1905x; 1.5493x over previous
#include <cuda_runtime.h>
#include <math.h>
#include <stdint.h>

// Problem constants (fixed shapes from reference)
#define H 112
#define W 112
#define HW 12544
#define CIN 64
#define OUTC 64
#define NB 8
#define NOFF 27          // 3*K*K
#define KK 576           // CIN * 9

// Scratch (static __device__ — no runtime allocation)
__device__ __align__(16) float g_xt[NB * HW * CIN];     // x in NHWC [N][H][W][C]
__device__ __align__(16) float g_wtt[9 * 64 * 64];      // main weights per-tap [t][o][c], tf32 bits
__device__ __align__(16) float g_owtt[9 * 32 * 64];     // offset weights [t][oc(pad32)][c], tf32 bits

#define CVT_TF32(u, f) asm("cvt.rna.tf32.f32 %0, %1;" : "=r"(u) : "f"(f))

#define MMA_TF32(d, a0, a1, a2, a3, b0, b1)                                   \
    asm volatile("mma.sync.aligned.m16n8k8.row.col.f32.tf32.tf32.f32 "        \
        "{%0,%1,%2,%3}, {%4,%5,%6,%7}, {%8,%9}, {%0,%1,%2,%3};"               \
        : "+f"((d)[0]), "+f"((d)[1]), "+f"((d)[2]), "+f"((d)[3])              \
        : "r"(a0), "r"(a1), "r"(a2), "r"(a3), "r"(b0), "r"(b1))

// ---------------------------------------------------------------------------
// Kernel 0: weight prep (both convs -> per-tap [rows][c] tf32 layouts)
// ---------------------------------------------------------------------------
__global__ void k_wprep(const float* __restrict__ w, const float* __restrict__ ow) {
    int idx = blockIdx.x * 256 + threadIdx.x;     // 0..36863
    if (idx < 9 * 32 * 64) {
        int t = idx >> 11, r = idx & 2047;
        int oc = r >> 6, c = r & 63;
        float v = (oc < NOFF) ? ow[oc * KK + c * 9 + t] : 0.f;
        uint32_t u; CVT_TF32(u, v);
        ((uint32_t*)g_owtt)[idx] = u;
    }
    {
        int t = idx >> 12, o = (idx >> 6) & 63, c = idx & 63;
        float v = w[o * KK + c * 9 + t];
        uint32_t u; CVT_TF32(u, v);
        ((uint32_t*)g_wtt)[idx] = u;
    }
}

// ---------------------------------------------------------------------------
// Kernel 1: NCHW -> NHWC transpose of x
// ---------------------------------------------------------------------------
__global__ void k_nhwc(const float* __restrict__ x) {
    __shared__ float tile[32][33];
    const int n = blockIdx.z;
    const int c0 = blockIdx.y * 32, p0 = blockIdx.x * 32;
    const float* xn = x + (size_t)n * CIN * HW;
    float* xtn = g_xt + (size_t)n * HW * CIN;
    const int tx = threadIdx.x & 31, ty = threadIdx.x >> 5;   // 32x8
    #pragma unroll
    for (int i = 0; i < 32; i += 8)
        tile[ty + i][tx] = xn[(size_t)(c0 + ty + i) * HW + p0 + tx];
    __syncthreads();
    #pragma unroll
    for (int i = 0; i < 32; i += 8)
        xtn[(size_t)(p0 + ty + i) * CIN + c0 + tx] = tile[tx][ty + i];
}

// ---------------------------------------------------------------------------
// Kernel 2 (fused): offset conv (tf32 mma) + deformable sampling + main GEMM.
// Tile: 16 wo x 8 ho = 128 px, 256 threads (8 warps), 2 CTAs/SM.
//
// SMEM map (dynamic, bytes):
//   [0      , 34816) val_s [128][68]   | phase1: patch [180][68] (48960 B,
//   [34816  , 52224) w_s   [64][68]    |         spills into w_s region)
//   [52224  , 66560) raw_s [128][28]   | phase1: owt_s [32][68] (8704 B)
//   [66560  , 68608) cw_s  [128] float4
//   [68608  , 70656) ci_s  [128] int4
//   [70656  , 70912) bs    [64]
//
// Phase 1: patch load -> 9-tap tf32 mma offset conv -> raw_s[px][27] (+bias)
// Phase 2: per tap: corners from raw_s; NHWC gather -> val_s; mma main GEMM.
// ---------------------------------------------------------------------------
__global__ void __launch_bounds__(256, 2)
k_main(const float* __restrict__ bias, const float* __restrict__ ob,
       float* __restrict__ out) {
    extern __shared__ unsigned char sm[];
    float*  val_s = (float*)sm;                  // [128][68]
    float*  w_s   = (float*)(sm + 34816);        // [64][68]
    float*  raw_s = (float*)(sm + 52224);        // [128][28]
    float*  owt_s = (float*)(sm + 52224);        // [32][68] (phase 1 only)
    float*  patch = (float*)sm;                  // [180][68] (phase 1 only)
    float4* cw_s  = (float4*)(sm + 66560);       // [128]
    int4*   ci_s  = (int4*)(sm + 68608);         // [128]
    float*  bs    = (float*)(sm + 70656);        // [64]

    const int tid = threadIdx.x;
    const int wo0 = blockIdx.x * 16, ho0 = blockIdx.y * 8, n = blockIdx.z;
    const int lane = tid & 31, warp = tid >> 5;
    const float* xtn = g_xt + (size_t)n * (HW * CIN);

    // mma lane mapping (shared by both phases)
    const int g = lane >> 2, ti = lane & 3;
    const int px0 = warp * 16;

    // ======================= PHASE 1: offset conv ==========================
    // patch load: 180 pos x 16 float4 = 2880 tasks (tf32-rounded)
    for (int i = tid; i < 2880; i += 256) {
        int pos = i >> 4, q = (i & 15) << 2;
        int gy = ho0 - 1 + pos / 18, gx = wo0 - 1 + pos % 18;
        uint4 u = make_uint4(0u, 0u, 0u, 0u);
        if (gy >= 0 && gy < H && gx >= 0 && gx < W) {
            float4 v = *(const float4*)(xtn + (size_t)(gy * W + gx) * CIN + q);
            CVT_TF32(u.x, v.x); CVT_TF32(u.y, v.y);
            CVT_TF32(u.z, v.z); CVT_TF32(u.w, v.w);
        }
        *(uint4*)(patch + pos * 68 + q) = u;
    }

    float aoff[4][4];
    #pragma unroll
    for (int j = 0; j < 4; j++)
        #pragma unroll
        for (int i = 0; i < 4; i++) aoff[j][i] = 0.f;

    for (int t = 0; t < 9; t++) {
        __syncthreads();   // patch ready (t==0) / previous mma done (t>0)
        // owt tile t -> owt_s [32][68]
        {
            const float4* src = (const float4*)(g_owtt + t * 2048);
            #pragma unroll
            for (int i = 0; i < 2; i++) {
                int q = tid + i * 256;           // 0..511
                float4 v = src[q];
                *(float4*)(owt_s + (q >> 4) * 68 + (q & 15) * 4) = v;
            }
        }
        __syncthreads();

        const int base = (warp + t / 3) * 18 + (t % 3);
        const uint32_t* pu = (const uint32_t*)patch;
        const uint32_t* ou = (const uint32_t*)owt_s;
        #pragma unroll
        for (int s = 0; s < 8; s++) {
            const int c0 = s * 8;
            const uint32_t* ap = pu + (base + g) * 68 + c0 + ti;
            uint32_t a0 = ap[0];
            uint32_t a2 = ap[4];
            uint32_t a1 = ap[8 * 68];
            uint32_t a3 = ap[8 * 68 + 4];
            #pragma unroll
            for (int j = 0; j < 4; j++) {
                const uint32_t* bp = ou + (j * 8 + g) * 68 + c0 + ti;
                MMA_TF32(aoff[j], a0, a1, a2, a3, bp[0], bp[4]);
            }
        }
    }
    __syncthreads();   // last tap's mma done before raw_s overwrites owt_s

    // write raw_s[px][27] (+ offset bias); load main bias to bs
    {
        const int r0 = px0 + g, r1 = px0 + 8 + g;
        #pragma unroll
        for (int j = 0; j < 4; j++) {
            int oc0 = 8 * j + 2 * ti;
            if (oc0 < NOFF) {
                float b = ob[oc0];
                raw_s[r0 * 28 + oc0] = aoff[j][0] + b;
                raw_s[r1 * 28 + oc0] = aoff[j][2] + b;
            }
            if (oc0 + 1 < NOFF) {
                float b = ob[oc0 + 1];
                raw_s[r0 * 28 + oc0 + 1] = aoff[j][1] + b;
                raw_s[r1 * 28 + oc0 + 1] = aoff[j][3] + b;
            }
        }
    }
    if (tid < 64) bs[tid] = bias[tid];

    // ======================= PHASE 2: main conv ============================
    const int sub = lane >> 4;
    const int c4 = (lane & 15) << 2;

    float acc[8][4];
    #pragma unroll
    for (int j = 0; j < 8; j++)
        #pragma unroll
        for (int i = 0; i < 4; i++) acc[j][i] = 0.f;

    for (int t = 0; t < 9; t++) {
        __syncthreads();   // raw_s ready (t==0) / previous stage C done (t>0)
        // ---- stage A: weights -> w_s (padded 68); corners from raw_s ----
        {
            const float4* wsrc = (const float4*)(g_wtt + t * 4096);
            const int o = tid >> 2, q = (tid & 3) * 4;
            #pragma unroll
            for (int i = 0; i < 4; i++) {
                float4 v = wsrc[o * 16 + q + i];
                *(float4*)(w_s + o * 68 + (q + i) * 4) = v;
            }
        }
        if (tid < 128) {
            const int y = tid >> 4, wxl = tid & 15;
            const int ho = ho0 + y, wo = wo0 + wxl;
            float dyv = raw_s[tid * 28 + 2 * t];
            float dxv = raw_s[tid * 28 + 2 * t + 1];
            float mv  = raw_s[tid * 28 + 18 + t];
            float m = 1.f / (1.f + expf(-mv));
            float py = dyv + (float)(ho - 1 + t / 3);
            float px = dxv + (float)(wo - 1 + t % 3);
            float y0f = floorf(py), x0f = floorf(px);
            float wy1 = py - y0f, wy0 = 1.f - wy1;
            float wx1 = px - x0f, wx0 = 1.f - wx1;
            int y0 = (int)y0f, x0 = (int)x0f;
            int y1 = y0 + 1, x1 = x0 + 1;
            bool vy0 = (y0 >= 0) && (y0 < H), vy1 = (y1 >= 0) && (y1 < H);
            bool vx0 = (x0 >= 0) && (x0 < W), vx1 = (x1 >= 0) && (x1 < W);
            float w00 = (vy0 && vx0) ? wy0 * wx0 * m : 0.f;
            float w01 = (vy0 && vx1) ? wy0 * wx1 * m : 0.f;
            float w10 = (vy1 && vx0) ? wy1 * wx0 * m : 0.f;
            float w11 = (vy1 && vx1) ? wy1 * wx1 * m : 0.f;
            int yc0 = min(max(y0, 0), H - 1), yc1 = min(max(y1, 0), H - 1);
            int xc0 = min(max(x0, 0), W - 1), xc1 = min(max(x1, 0), W - 1);
            cw_s[tid] = make_float4(w00, w01, w10, w11);
            ci_s[tid] = make_int4(yc0 * W + xc0, yc0 * W + xc1, yc1 * W + xc0, yc1 * W + xc1);
        }
        __syncthreads();

        // ---- stage B: coalesced NHWC bilinear gather -> val_s (tf32) ----
        #pragma unroll 2
        for (int it = 0; it < 8; it++) {
            int px = warp * 16 + it * 2 + sub;      // 0..127
            float4 w4 = cw_s[px];
            int4 i4 = ci_s[px];
            float4 g0 = *(const float4*)(xtn + (size_t)i4.x * CIN + c4);
            float4 g1 = *(const float4*)(xtn + (size_t)i4.y * CIN + c4);
            float4 g2 = *(const float4*)(xtn + (size_t)i4.z * CIN + c4);
            float4 g3 = *(const float4*)(xtn + (size_t)i4.w * CIN + c4);
            float4 v;
            v.x = fmaf(w4.w, g3.x, fmaf(w4.z, g2.x, fmaf(w4.y, g1.x, w4.x * g0.x)));
            v.y = fmaf(w4.w, g3.y, fmaf(w4.z, g2.y, fmaf(w4.y, g1.y, w4.x * g0.y)));
            v.z = fmaf(w4.w, g3.z, fmaf(w4.z, g2.z, fmaf(w4.y, g1.z, w4.x * g0.z)));
            v.w = fmaf(w4.w, g3.w, fmaf(w4.z, g2.w, fmaf(w4.y, g1.w, w4.x * g0.w)));
            uint4 u;
            CVT_TF32(u.x, v.x); CVT_TF32(u.y, v.y);
            CVT_TF32(u.z, v.z); CVT_TF32(u.w, v.w);
            *(uint4*)(val_s + px * 68 + c4) = u;
        }
        __syncthreads();

        // ---- stage C: mma.sync tf32 over this chunk's K=64 ----
        {
            const uint32_t* vsu = (const uint32_t*)val_s;
            const uint32_t* wsu = (const uint32_t*)w_s;
            #pragma unroll
            for (int s = 0; s < 8; s++) {
                const int c0 = s * 8;
                const uint32_t* ap = vsu + (px0 + g) * 68 + c0 + ti;
                uint32_t a0 = ap[0];
                uint32_t a2 = ap[4];
                uint32_t a1 = ap[8 * 68];
                uint32_t a3 = ap[8 * 68 + 4];
                #pragma unroll
                for (int j = 0; j < 8; j++) {
                    const uint32_t* bp = wsu + (j * 8 + g) * 68 + c0 + ti;
                    MMA_TF32(acc[j], a0, a1, a2, a3, bp[0], bp[4]);
                }
            }
        }
    }

    // ---- epilogue: D frags + bias -> out (NCHW) ----
    const int ho = ho0 + warp;
    float* op = out + (((size_t)n * OUTC) * H + ho) * W + wo0;
    #pragma unroll
    for (int j = 0; j < 8; j++) {
        int o0 = 8 * j + 2 * ti;
        float b0v = bs[o0], b1v = bs[o0 + 1];
        op[(size_t)o0 * HW + g]            = acc[j][0] + b0v;
        op[(size_t)(o0 + 1) * HW + g]      = acc[j][1] + b1v;
        op[(size_t)o0 * HW + g + 8]        = acc[j][2] + b0v;
        op[(size_t)(o0 + 1) * HW + g + 8]  = acc[j][3] + b1v;
    }
}

// ---------------------------------------------------------------------------
extern "C" void kernel_launch(void* const* d_in, const int* in_sizes, int n_in,
                              void* d_out, int out_size) {
    (void)in_sizes; (void)n_in; (void)out_size;
    const float* x        = (const float*)d_in[0];
    const float* weight   = (const float*)d_in[1];
    const float* bias     = (const float*)d_in[2];
    const float* offset_w = (const float*)d_in[3];
    const float* offset_b = (const float*)d_in[4];
    float* out = (float*)d_out;

    cudaFuncSetAttribute(k_main, cudaFuncAttributeMaxDynamicSharedMemorySize, 70912);

    k_wprep<<<144, 256>>>(weight, offset_w);
    k_nhwc<<<dim3(392, 2, 8), 256>>>(x);
    k_main<<<dim3(7, 14, 8), 256, 70912>>>(bias, offset_b, out);
}

// round 9
// speedup vs baseline: 8.2543x; 1.1480x over previous
#include <cuda_runtime.h>
#include <math.h>
#include <stdint.h>

// Problem constants (fixed shapes from reference)
#define H 112
#define W 112
#define HW 12544
#define CIN 64
#define OUTC 64
#define NB 8
#define NOFF 27          // 3*K*K
#define KK 576           // CIN * 9

// Scratch (static __device__ — no runtime allocation)
__device__ __align__(16) float g_xt[NB * HW * CIN];     // x in NHWC [N][H][W][C]
__device__ __align__(16) float g_wtt[9 * 64 * 64];      // main weights per-tap [t][o][c], tf32 bits
__device__ __align__(16) float g_owtt[9 * 32 * 64];     // offset weights [t][oc(pad32)][c], tf32 bits

#define CVT_TF32(u, f) asm("cvt.rna.tf32.f32 %0, %1;" : "=r"(u) : "f"(f))

#define MMA_TF32(d, a0, a1, a2, a3, b0, b1)                                   \
    asm volatile("mma.sync.aligned.m16n8k8.row.col.f32.tf32.tf32.f32 "        \
        "{%0,%1,%2,%3}, {%4,%5,%6,%7}, {%8,%9}, {%0,%1,%2,%3};"               \
        : "+f"((d)[0]), "+f"((d)[1]), "+f"((d)[2]), "+f"((d)[3])              \
        : "r"(a0), "r"(a1), "r"(a2), "r"(a3), "r"(b0), "r"(b1))

// ---------------------------------------------------------------------------
// Kernel 0: weight prep (both convs -> per-tap [rows][c] tf32 layouts)
// ---------------------------------------------------------------------------
__global__ void k_wprep(const float* __restrict__ w, const float* __restrict__ ow) {
    int idx = blockIdx.x * 256 + threadIdx.x;     // 0..36863
    if (idx < 9 * 32 * 64) {
        int t = idx >> 11, r = idx & 2047;
        int oc = r >> 6, c = r & 63;
        float v = (oc < NOFF) ? ow[oc * KK + c * 9 + t] : 0.f;
        uint32_t u; CVT_TF32(u, v);
        ((uint32_t*)g_owtt)[idx] = u;
    }
    {
        int t = idx >> 12, o = (idx >> 6) & 63, c = idx & 63;
        float v = w[o * KK + c * 9 + t];
        uint32_t u; CVT_TF32(u, v);
        ((uint32_t*)g_wtt)[idx] = u;
    }
}

// ---------------------------------------------------------------------------
// Kernel 1: NCHW -> NHWC transpose of x
// ---------------------------------------------------------------------------
__global__ void k_nhwc(const float* __restrict__ x) {
    __shared__ float tile[32][33];
    const int n = blockIdx.z;
    const int c0 = blockIdx.y * 32, p0 = blockIdx.x * 32;
    const float* xn = x + (size_t)n * CIN * HW;
    float* xtn = g_xt + (size_t)n * HW * CIN;
    const int tx = threadIdx.x & 31, ty = threadIdx.x >> 5;   // 32x8
    #pragma unroll
    for (int i = 0; i < 32; i += 8)
        tile[ty + i][tx] = xn[(size_t)(c0 + ty + i) * HW + p0 + tx];
    __syncthreads();
    #pragma unroll
    for (int i = 0; i < 32; i += 8)
        xtn[(size_t)(p0 + ty + i) * CIN + c0 + tx] = tile[tx][ty + i];
}

// ---------------------------------------------------------------------------
// Kernel 2 (fused): offset conv (tf32 mma) + deformable sampling + main GEMM.
// Tile: 16 wo x 4 ho = 64 px, 128 threads (4 warps), 4 CTAs/SM.
//
// SMEM map (dynamic, bytes):
//   [0     , 17408) val_s [64][68]    | phase1: patch [108][68] = 29376 B
//   [17408 , 34816) w_s   [64][68]    |         (spills into w_s region)
//   [34816 , 43520) raw_s [64][28]=7168 | phase1: owt_s [32][68] = 8704 B
//   [43520 , 44544) cw_s  [64] float4
//   [44544 , 45568) ci_s  [64] int4
//   [45568 , 45824) bs    [64]
//
// Phase 1: patch load -> 9-tap tf32 mma offset conv -> raw_s[px][27] (+bias)
//          (warp w = 16 px (ho row w) x 32 oc)
// Phase 2: per tap: corners from raw_s; NHWC gather -> val_s; mma main GEMM
//          (warp w = 32 px x 32 o: px0=(w&1)*32, o0=(w>>1)*32)
// ---------------------------------------------------------------------------
__global__ void __launch_bounds__(128, 4)
k_main(const float* __restrict__ bias, const float* __restrict__ ob,
       float* __restrict__ out) {
    extern __shared__ unsigned char sm[];
    float*  val_s = (float*)sm;                  // [64][68]
    float*  w_s   = (float*)(sm + 17408);        // [64][68]
    float*  raw_s = (float*)(sm + 34816);        // [64][28]
    float*  owt_s = (float*)(sm + 34816);        // [32][68] (phase 1 only)
    float*  patch = (float*)sm;                  // [108][68] (phase 1 only)
    float4* cw_s  = (float4*)(sm + 43520);       // [64]
    int4*   ci_s  = (int4*)(sm + 44544);         // [64]
    float*  bs    = (float*)(sm + 45568);        // [64]

    const int tid = threadIdx.x;
    const int wo0 = blockIdx.x * 16, ho0 = blockIdx.y * 4, n = blockIdx.z;
    const int lane = tid & 31, warp = tid >> 5;
    const float* xtn = g_xt + (size_t)n * (HW * CIN);

    // mma lane mapping (shared by both phases)
    const int g = lane >> 2, ti = lane & 3;

    // ======================= PHASE 1: offset conv ==========================
    // patch: (4+2) rows x 18 cols = 108 pos x 16 float4 = 1728 tasks
    for (int i = tid; i < 1728; i += 128) {
        int pos = i >> 4, q = (i & 15) << 2;
        int gy = ho0 - 1 + pos / 18, gx = wo0 - 1 + pos % 18;
        uint4 u = make_uint4(0u, 0u, 0u, 0u);
        if (gy >= 0 && gy < H && gx >= 0 && gx < W) {
            float4 v = *(const float4*)(xtn + (size_t)(gy * W + gx) * CIN + q);
            CVT_TF32(u.x, v.x); CVT_TF32(u.y, v.y);
            CVT_TF32(u.z, v.z); CVT_TF32(u.w, v.w);
        }
        *(uint4*)(patch + pos * 68 + q) = u;
    }

    float aoff[4][4];
    #pragma unroll
    for (int j = 0; j < 4; j++)
        #pragma unroll
        for (int i = 0; i < 4; i++) aoff[j][i] = 0.f;

    for (int t = 0; t < 9; t++) {
        __syncthreads();   // patch ready (t==0) / previous mma done (t>0)
        // owt tile t -> owt_s [32][68]
        {
            const float4* src = (const float4*)(g_owtt + t * 2048);
            #pragma unroll
            for (int i = 0; i < 4; i++) {
                int q = tid + i * 128;           // 0..511
                float4 v = src[q];
                *(float4*)(owt_s + (q >> 4) * 68 + (q & 15) * 4) = v;
            }
        }
        __syncthreads();

        const int base = (warp + t / 3) * 18 + (t % 3);
        const uint32_t* pu = (const uint32_t*)patch;
        const uint32_t* ou = (const uint32_t*)owt_s;
        #pragma unroll
        for (int s = 0; s < 8; s++) {
            const int c0 = s * 8;
            const uint32_t* ap = pu + (base + g) * 68 + c0 + ti;
            uint32_t a0 = ap[0];
            uint32_t a2 = ap[4];
            uint32_t a1 = ap[8 * 68];
            uint32_t a3 = ap[8 * 68 + 4];
            #pragma unroll
            for (int j = 0; j < 4; j++) {
                const uint32_t* bp = ou + (j * 8 + g) * 68 + c0 + ti;
                MMA_TF32(aoff[j], a0, a1, a2, a3, bp[0], bp[4]);
            }
        }
    }
    __syncthreads();   // last tap's mma done before raw_s overwrites owt_s

    // write raw_s[px][27] (+ offset bias); warp w owns px rows w*16+g, +8
    {
        const int r0 = warp * 16 + g, r1 = warp * 16 + 8 + g;
        #pragma unroll
        for (int j = 0; j < 4; j++) {
            int oc0 = 8 * j + 2 * ti;
            if (oc0 < NOFF) {
                float b = ob[oc0];
                raw_s[r0 * 28 + oc0] = aoff[j][0] + b;
                raw_s[r1 * 28 + oc0] = aoff[j][2] + b;
            }
            if (oc0 + 1 < NOFF) {
                float b = ob[oc0 + 1];
                raw_s[r0 * 28 + oc0 + 1] = aoff[j][1] + b;
                raw_s[r1 * 28 + oc0 + 1] = aoff[j][3] + b;
            }
        }
    }
    if (tid < 64) bs[tid] = bias[tid];

    // ======================= PHASE 2: main conv ============================
    const int sub = lane >> 4;
    const int c4 = (lane & 15) << 2;
    const int px0 = (warp & 1) * 32;
    const int o0  = (warp >> 1) * 32;

    float acc[2][4][4];
    #pragma unroll
    for (int mt = 0; mt < 2; mt++)
        #pragma unroll
        for (int j = 0; j < 4; j++)
            #pragma unroll
            for (int i = 0; i < 4; i++) acc[mt][j][i] = 0.f;

    for (int t = 0; t < 9; t++) {
        __syncthreads();   // raw_s ready (t==0) / previous stage C done (t>0)
        // ---- stage A: weights -> w_s (padded 68); corners from raw_s ----
        {
            const float4* wsrc = (const float4*)(g_wtt + t * 4096);
            #pragma unroll
            for (int i = 0; i < 8; i++) {
                int q = tid + i * 128;           // 0..1023
                float4 v = wsrc[q];
                *(float4*)(w_s + (q >> 4) * 68 + (q & 15) * 4) = v;
            }
        }
        if (tid < 64) {
            const int y = tid >> 4, wxl = tid & 15;
            const int ho = ho0 + y, wo = wo0 + wxl;
            float dyv = raw_s[tid * 28 + 2 * t];
            float dxv = raw_s[tid * 28 + 2 * t + 1];
            float mv  = raw_s[tid * 28 + 18 + t];
            float m = 1.f / (1.f + expf(-mv));
            float py = dyv + (float)(ho - 1 + t / 3);
            float px = dxv + (float)(wo - 1 + t % 3);
            float y0f = floorf(py), x0f = floorf(px);
            float wy1 = py - y0f, wy0 = 1.f - wy1;
            float wx1 = px - x0f, wx0 = 1.f - wx1;
            int y0 = (int)y0f, x0 = (int)x0f;
            int y1 = y0 + 1, x1 = x0 + 1;
            bool vy0 = (y0 >= 0) && (y0 < H), vy1 = (y1 >= 0) && (y1 < H);
            bool vx0 = (x0 >= 0) && (x0 < W), vx1 = (x1 >= 0) && (x1 < W);
            float w00 = (vy0 && vx0) ? wy0 * wx0 * m : 0.f;
            float w01 = (vy0 && vx1) ? wy0 * wx1 * m : 0.f;
            float w10 = (vy1 && vx0) ? wy1 * wx0 * m : 0.f;
            float w11 = (vy1 && vx1) ? wy1 * wx1 * m : 0.f;
            int yc0 = min(max(y0, 0), H - 1), yc1 = min(max(y1, 0), H - 1);
            int xc0 = min(max(x0, 0), W - 1), xc1 = min(max(x1, 0), W - 1);
            cw_s[tid] = make_float4(w00, w01, w10, w11);
            ci_s[tid] = make_int4(yc0 * W + xc0, yc0 * W + xc1, yc1 * W + xc0, yc1 * W + xc1);
        }
        __syncthreads();

        // ---- stage B: coalesced NHWC bilinear gather -> val_s (tf32) ----
        #pragma unroll 2
        for (int it = 0; it < 8; it++) {
            int px = warp * 16 + it * 2 + sub;      // 0..63
            float4 w4 = cw_s[px];
            int4 i4 = ci_s[px];
            float4 g0 = *(const float4*)(xtn + (size_t)i4.x * CIN + c4);
            float4 g1 = *(const float4*)(xtn + (size_t)i4.y * CIN + c4);
            float4 g2 = *(const float4*)(xtn + (size_t)i4.z * CIN + c4);
            float4 g3 = *(const float4*)(xtn + (size_t)i4.w * CIN + c4);
            float4 v;
            v.x = fmaf(w4.w, g3.x, fmaf(w4.z, g2.x, fmaf(w4.y, g1.x, w4.x * g0.x)));
            v.y = fmaf(w4.w, g3.y, fmaf(w4.z, g2.y, fmaf(w4.y, g1.y, w4.x * g0.y)));
            v.z = fmaf(w4.w, g3.z, fmaf(w4.z, g2.z, fmaf(w4.y, g1.z, w4.x * g0.z)));
            v.w = fmaf(w4.w, g3.w, fmaf(w4.z, g2.w, fmaf(w4.y, g1.w, w4.x * g0.w)));
            uint4 u;
            CVT_TF32(u.x, v.x); CVT_TF32(u.y, v.y);
            CVT_TF32(u.z, v.z); CVT_TF32(u.w, v.w);
            *(uint4*)(val_s + px * 68 + c4) = u;
        }
        __syncthreads();

        // ---- stage C: mma.sync tf32, warp tile 32 px x 32 o ----
        {
            const uint32_t* vsu = (const uint32_t*)val_s;
            const uint32_t* wsu = (const uint32_t*)w_s;
            #pragma unroll
            for (int s = 0; s < 8; s++) {
                const int c0 = s * 8;
                #pragma unroll
                for (int mt = 0; mt < 2; mt++) {
                    const uint32_t* ap = vsu + (px0 + 16 * mt + g) * 68 + c0 + ti;
                    uint32_t a0 = ap[0];
                    uint32_t a2 = ap[4];
                    uint32_t a1 = ap[8 * 68];
                    uint32_t a3 = ap[8 * 68 + 4];
                    #pragma unroll
                    for (int j = 0; j < 4; j++) {
                        const uint32_t* bp = wsu + (o0 + 8 * j + g) * 68 + c0 + ti;
                        MMA_TF32(acc[mt][j], a0, a1, a2, a3, bp[0], bp[4]);
                    }
                }
            }
        }
    }

    // ---- epilogue: D frags + bias -> out (NCHW) ----
    #pragma unroll
    for (int mt = 0; mt < 2; mt++) {
        const int ho = ho0 + 2 * (warp & 1) + mt;
        float* op = out + (((size_t)n * OUTC) * H + ho) * W + wo0;
        #pragma unroll
        for (int j = 0; j < 4; j++) {
            int oc = o0 + 8 * j + 2 * ti;
            float b0v = bs[oc], b1v = bs[oc + 1];
            op[(size_t)oc * HW + g]            = acc[mt][j][0] + b0v;
            op[(size_t)(oc + 1) * HW + g]      = acc[mt][j][1] + b1v;
            op[(size_t)oc * HW + g + 8]        = acc[mt][j][2] + b0v;
            op[(size_t)(oc + 1) * HW + g + 8]  = acc[mt][j][3] + b1v;
        }
    }
}

// ---------------------------------------------------------------------------
extern "C" void kernel_launch(void* const* d_in, const int* in_sizes, int n_in,
                              void* d_out, int out_size) {
    (void)in_sizes; (void)n_in; (void)out_size;
    const float* x        = (const float*)d_in[0];
    const float* weight   = (const float*)d_in[1];
    const float* bias     = (const float*)d_in[2];
    const float* offset_w = (const float*)d_in[3];
    const float* offset_b = (const float*)d_in[4];
    float* out = (float*)d_out;

    cudaFuncSetAttribute(k_main, cudaFuncAttributeMaxDynamicSharedMemorySize, 45824);

    k_wprep<<<144, 256>>>(weight, offset_w);
    k_nhwc<<<dim3(392, 2, 8), 256>>>(x);
    k_main<<<dim3(7, 28, 8), 128, 45824>>>(bias, offset_b, out);
}

// round 10
// speedup vs baseline: 10.8659x; 1.3164x over previous
#include <cuda_runtime.h>
#include <cuda_fp16.h>
#include <math.h>
#include <stdint.h>

// Problem constants (fixed shapes from reference)
#define H 112
#define W 112
#define HW 12544
#define CIN 64
#define OUTC 64
#define NB 8
#define NOFF 27          // 3*K*K
#define KK 576           // CIN * 9

// Scratch (static __device__ — no runtime allocation)
__device__ __align__(16) float    g_xt[NB * HW * CIN];   // x in NHWC [N][H][W][C]
__device__ __align__(16) uint16_t g_wtt[9 * 64 * 64];    // main weights [t][o][c], fp16
__device__ __align__(16) uint16_t g_owtt[9 * 32 * 64];   // offset weights [t][oc(pad32)][c], fp16

#define MMA_F16(d, a0, a1, a2, a3, b0, b1)                                    \
    asm volatile("mma.sync.aligned.m16n8k16.row.col.f32.f16.f16.f32 "         \
        "{%0,%1,%2,%3}, {%4,%5,%6,%7}, {%8,%9}, {%0,%1,%2,%3};"               \
        : "+f"((d)[0]), "+f"((d)[1]), "+f"((d)[2]), "+f"((d)[3])              \
        : "r"(a0), "r"(a1), "r"(a2), "r"(a3), "r"(b0), "r"(b1))

// pack 2 floats -> half2 bits
__device__ __forceinline__ uint32_t f2h2(float lo, float hi) {
    __half2 h = __floats2half2_rn(lo, hi);
    return *(uint32_t*)&h;
}

// ---------------------------------------------------------------------------
// Kernel 0: weight prep (both convs -> per-tap [rows][c] fp16 layouts)
// ---------------------------------------------------------------------------
__global__ void k_wprep(const float* __restrict__ w, const float* __restrict__ ow) {
    int idx = blockIdx.x * 256 + threadIdx.x;     // 0..36863
    if (idx < 9 * 32 * 64) {
        int t = idx >> 11, oc = (idx >> 6) & 31, c = idx & 63;
        float v = (oc < NOFF) ? ow[oc * KK + c * 9 + t] : 0.f;
        __half h = __float2half_rn(v);
        g_owtt[idx] = *(uint16_t*)&h;
    }
    {
        int t = idx >> 12, o = (idx >> 6) & 63, c = idx & 63;
        float v = w[o * KK + c * 9 + t];
        __half h = __float2half_rn(v);
        g_wtt[idx] = *(uint16_t*)&h;
    }
}

// ---------------------------------------------------------------------------
// Kernel 1: NCHW -> NHWC transpose of x
// ---------------------------------------------------------------------------
__global__ void k_nhwc(const float* __restrict__ x) {
    __shared__ float tile[32][33];
    const int n = blockIdx.z;
    const int c0 = blockIdx.y * 32, p0 = blockIdx.x * 32;
    const float* xn = x + (size_t)n * CIN * HW;
    float* xtn = g_xt + (size_t)n * HW * CIN;
    const int tx = threadIdx.x & 31, ty = threadIdx.x >> 5;   // 32x8
    #pragma unroll
    for (int i = 0; i < 32; i += 8)
        tile[ty + i][tx] = xn[(size_t)(c0 + ty + i) * HW + p0 + tx];
    __syncthreads();
    #pragma unroll
    for (int i = 0; i < 32; i += 8)
        xtn[(size_t)(p0 + ty + i) * CIN + c0 + tx] = tile[tx][ty + i];
}

// ---------------------------------------------------------------------------
// Kernel 2 (fused): offset conv (fp16 mma) + deformable sampling + main GEMM.
// Tile: 16 wo x 4 ho = 64 px, 128 threads (4 warps), 5 CTAs/SM.
//
// SMEM (bytes), row stride 72 halves = 144 B (bank-perfect: 4g+ti+8s):
//   [0     ,  9216) val_s [64][72] half   | phase1: patch [108][72] half
//   [9216  , 18432) w_s   [64][72] half   |         (15552 B, spills into w_s)
//   [18432 , 25600) raw_s [64][28] f32    | phase1: owt_s [32][72] half (4608 B)
//   [25600 , 26624) cw_s  [64] float4
//   [26624 , 27648) ci_s  [64] int4
//   [27648 , 27904) bs    [64] f32
//
// Phase 1: patch load -> 9-tap fp16 mma offset conv -> raw_s[px][27] (+bias)
// Phase 2: per tap: corners; NHWC gather -> val_s (fp16); m16n8k16 main GEMM
//          (warp = 32 px x 32 o)
// ---------------------------------------------------------------------------
__global__ void __launch_bounds__(128, 5)
k_main(const float* __restrict__ bias, const float* __restrict__ ob,
       float* __restrict__ out) {
    extern __shared__ unsigned char sm[];
    uint16_t* val_h = (uint16_t*)sm;                 // [64][72]
    uint16_t* w_h   = (uint16_t*)(sm + 9216);        // [64][72]
    float*    raw_s = (float*)(sm + 18432);          // [64][28]
    uint16_t* owt_h = (uint16_t*)(sm + 18432);       // [32][72] (phase 1)
    uint16_t* patch = (uint16_t*)sm;                 // [108][72] (phase 1)
    float4*   cw_s  = (float4*)(sm + 25600);         // [64]
    int4*     ci_s  = (int4*)(sm + 26624);           // [64]
    float*    bs    = (float*)(sm + 27648);          // [64]

    const int tid = threadIdx.x;
    const int wo0 = blockIdx.x * 16, ho0 = blockIdx.y * 4, n = blockIdx.z;
    const int lane = tid & 31, warp = tid >> 5;
    const float* xtn = g_xt + (size_t)n * (HW * CIN);

    // mma lane mapping (shared by both phases)
    const int g = lane >> 2, ti = lane & 3;

    // ======================= PHASE 1: offset conv ==========================
    // patch: (4+2) rows x 18 cols = 108 pos x 16 ch-groups = 1728 tasks
    for (int i = tid; i < 1728; i += 128) {
        int pos = i >> 4, q = i & 15;                // 4 channels per task
        int gy = ho0 - 1 + pos / 18, gx = wo0 - 1 + pos % 18;
        uint2 u = make_uint2(0u, 0u);
        if (gy >= 0 && gy < H && gx >= 0 && gx < W) {
            float4 v = *(const float4*)(xtn + (size_t)(gy * W + gx) * CIN + q * 4);
            u.x = f2h2(v.x, v.y);
            u.y = f2h2(v.z, v.w);
        }
        *(uint2*)(patch + pos * 72 + q * 4) = u;
    }

    float aoff[4][4];
    #pragma unroll
    for (int j = 0; j < 4; j++)
        #pragma unroll
        for (int i = 0; i < 4; i++) aoff[j][i] = 0.f;

    for (int t = 0; t < 9; t++) {
        __syncthreads();   // patch ready (t==0) / previous mma done (t>0)
        // owt tile t -> owt_h [32][72]
        {
            const float4* src = (const float4*)(g_owtt + t * 2048);
            #pragma unroll
            for (int i = 0; i < 2; i++) {
                int q = tid + i * 128;               // 0..255 (16B = 8 halves)
                float4 v = src[q];
                *(float4*)(owt_h + (q >> 3) * 72 + (q & 7) * 8) = v;
            }
        }
        __syncthreads();

        const int base = (warp + t / 3) * 18 + (t % 3);
        #pragma unroll
        for (int s = 0; s < 4; s++) {
            const int ko = 16 * s + 2 * ti;
            const uint16_t* ap0 = patch + (base + g) * 72 + ko;
            const uint16_t* ap1 = patch + (base + g + 8) * 72 + ko;
            uint32_t a0 = *(const uint32_t*)ap0;
            uint32_t a2 = *(const uint32_t*)(ap0 + 8);
            uint32_t a1 = *(const uint32_t*)ap1;
            uint32_t a3 = *(const uint32_t*)(ap1 + 8);
            #pragma unroll
            for (int j = 0; j < 4; j++) {
                const uint16_t* bp = owt_h + (j * 8 + g) * 72 + ko;
                uint32_t b0 = *(const uint32_t*)bp;
                uint32_t b1 = *(const uint32_t*)(bp + 8);
                MMA_F16(aoff[j], a0, a1, a2, a3, b0, b1);
            }
        }
    }
    __syncthreads();   // last tap's mma done before raw_s overwrites owt_h

    // write raw_s[px][27] (+ offset bias); warp w owns px rows w*16+g, +8
    {
        const int r0 = warp * 16 + g, r1 = warp * 16 + 8 + g;
        #pragma unroll
        for (int j = 0; j < 4; j++) {
            int oc0 = 8 * j + 2 * ti;
            if (oc0 < NOFF) {
                float b = ob[oc0];
                raw_s[r0 * 28 + oc0] = aoff[j][0] + b;
                raw_s[r1 * 28 + oc0] = aoff[j][2] + b;
            }
            if (oc0 + 1 < NOFF) {
                float b = ob[oc0 + 1];
                raw_s[r0 * 28 + oc0 + 1] = aoff[j][1] + b;
                raw_s[r1 * 28 + oc0 + 1] = aoff[j][3] + b;
            }
        }
    }
    if (tid < 64) bs[tid] = bias[tid];

    // ======================= PHASE 2: main conv ============================
    const int sub = lane >> 4;
    const int c4 = (lane & 15) << 2;
    const int px0 = (warp & 1) * 32;
    const int o0  = (warp >> 1) * 32;

    float acc[2][4][4];
    #pragma unroll
    for (int mt = 0; mt < 2; mt++)
        #pragma unroll
        for (int j = 0; j < 4; j++)
            #pragma unroll
            for (int i = 0; i < 4; i++) acc[mt][j][i] = 0.f;

    for (int t = 0; t < 9; t++) {
        __syncthreads();   // raw_s ready (t==0) / previous stage C done (t>0)
        // ---- stage A: weights -> w_h (72-stride); corners from raw_s ----
        {
            const float4* wsrc = (const float4*)(g_wtt + t * 4096);
            #pragma unroll
            for (int i = 0; i < 4; i++) {
                int q = tid + i * 128;               // 0..511 (16B = 8 halves)
                float4 v = wsrc[q];
                *(float4*)(w_h + (q >> 3) * 72 + (q & 7) * 8) = v;
            }
        }
        if (tid < 64) {
            const int y = tid >> 4, wxl = tid & 15;
            const int ho = ho0 + y, wo = wo0 + wxl;
            float dyv = raw_s[tid * 28 + 2 * t];
            float dxv = raw_s[tid * 28 + 2 * t + 1];
            float mv  = raw_s[tid * 28 + 18 + t];
            float m = 1.f / (1.f + expf(-mv));
            float py = dyv + (float)(ho - 1 + t / 3);
            float px = dxv + (float)(wo - 1 + t % 3);
            float y0f = floorf(py), x0f = floorf(px);
            float wy1 = py - y0f, wy0 = 1.f - wy1;
            float wx1 = px - x0f, wx0 = 1.f - wx1;
            int y0 = (int)y0f, x0 = (int)x0f;
            int y1 = y0 + 1, x1 = x0 + 1;
            bool vy0 = (y0 >= 0) && (y0 < H), vy1 = (y1 >= 0) && (y1 < H);
            bool vx0 = (x0 >= 0) && (x0 < W), vx1 = (x1 >= 0) && (x1 < W);
            float w00 = (vy0 && vx0) ? wy0 * wx0 * m : 0.f;
            float w01 = (vy0 && vx1) ? wy0 * wx1 * m : 0.f;
            float w10 = (vy1 && vx0) ? wy1 * wx0 * m : 0.f;
            float w11 = (vy1 && vx1) ? wy1 * wx1 * m : 0.f;
            int yc0 = min(max(y0, 0), H - 1), yc1 = min(max(y1, 0), H - 1);
            int xc0 = min(max(x0, 0), W - 1), xc1 = min(max(x1, 0), W - 1);
            cw_s[tid] = make_float4(w00, w01, w10, w11);
            ci_s[tid] = make_int4(yc0 * W + xc0, yc0 * W + xc1, yc1 * W + xc0, yc1 * W + xc1);
        }
        __syncthreads();

        // ---- stage B: coalesced NHWC bilinear gather -> val_h (fp16) ----
        #pragma unroll 2
        for (int it = 0; it < 8; it++) {
            int px = warp * 16 + it * 2 + sub;       // 0..63
            float4 w4 = cw_s[px];
            int4 i4 = ci_s[px];
            float4 g0 = *(const float4*)(xtn + (size_t)i4.x * CIN + c4);
            float4 g1 = *(const float4*)(xtn + (size_t)i4.y * CIN + c4);
            float4 g2 = *(const float4*)(xtn + (size_t)i4.z * CIN + c4);
            float4 g3 = *(const float4*)(xtn + (size_t)i4.w * CIN + c4);
            float4 v;
            v.x = fmaf(w4.w, g3.x, fmaf(w4.z, g2.x, fmaf(w4.y, g1.x, w4.x * g0.x)));
            v.y = fmaf(w4.w, g3.y, fmaf(w4.z, g2.y, fmaf(w4.y, g1.y, w4.x * g0.y)));
            v.z = fmaf(w4.w, g3.z, fmaf(w4.z, g2.z, fmaf(w4.y, g1.z, w4.x * g0.z)));
            v.w = fmaf(w4.w, g3.w, fmaf(w4.z, g2.w, fmaf(w4.y, g1.w, w4.x * g0.w)));
            uint2 u;
            u.x = f2h2(v.x, v.y);
            u.y = f2h2(v.z, v.w);
            *(uint2*)(val_h + px * 72 + c4) = u;
        }
        __syncthreads();

        // ---- stage C: m16n8k16 fp16 mma, warp tile 32 px x 32 o ----
        #pragma unroll
        for (int s = 0; s < 4; s++) {
            const int ko = 16 * s + 2 * ti;
            #pragma unroll
            for (int mt = 0; mt < 2; mt++) {
                const uint16_t* ap0 = val_h + (px0 + 16 * mt + g) * 72 + ko;
                const uint16_t* ap1 = val_h + (px0 + 16 * mt + g + 8) * 72 + ko;
                uint32_t a0 = *(const uint32_t*)ap0;
                uint32_t a2 = *(const uint32_t*)(ap0 + 8);
                uint32_t a1 = *(const uint32_t*)ap1;
                uint32_t a3 = *(const uint32_t*)(ap1 + 8);
                #pragma unroll
                for (int j = 0; j < 4; j++) {
                    const uint16_t* bp = w_h + (o0 + 8 * j + g) * 72 + ko;
                    uint32_t b0 = *(const uint32_t*)bp;
                    uint32_t b1 = *(const uint32_t*)(bp + 8);
                    MMA_F16(acc[mt][j], a0, a1, a2, a3, b0, b1);
                }
            }
        }
    }

    // ---- epilogue: D frags + bias -> out (NCHW) ----
    #pragma unroll
    for (int mt = 0; mt < 2; mt++) {
        const int ho = ho0 + 2 * (warp & 1) + mt;
        float* op = out + (((size_t)n * OUTC) * H + ho) * W + wo0;
        #pragma unroll
        for (int j = 0; j < 4; j++) {
            int oc = o0 + 8 * j + 2 * ti;
            float b0v = bs[oc], b1v = bs[oc + 1];
            op[(size_t)oc * HW + g]            = acc[mt][j][0] + b0v;
            op[(size_t)(oc + 1) * HW + g]      = acc[mt][j][1] + b1v;
            op[(size_t)oc * HW + g + 8]        = acc[mt][j][2] + b0v;
            op[(size_t)(oc + 1) * HW + g + 8]  = acc[mt][j][3] + b1v;
        }
    }
}

// ---------------------------------------------------------------------------
extern "C" void kernel_launch(void* const* d_in, const int* in_sizes, int n_in,
                              void* d_out, int out_size) {
    (void)in_sizes; (void)n_in; (void)out_size;
    const float* x        = (const float*)d_in[0];
    const float* weight   = (const float*)d_in[1];
    const float* bias     = (const float*)d_in[2];
    const float* offset_w = (const float*)d_in[3];
    const float* offset_b = (const float*)d_in[4];
    float* out = (float*)d_out;

    cudaFuncSetAttribute(k_main, cudaFuncAttributeMaxDynamicSharedMemorySize, 27904);

    k_wprep<<<144, 256>>>(weight, offset_w);
    k_nhwc<<<dim3(392, 2, 8), 256>>>(x);
    k_main<<<dim3(7, 28, 8), 128, 27904>>>(bias, offset_b, out);
}

// round 12
// speedup vs baseline: 14.1217x; 1.2996x over previous
#include <cuda_runtime.h>
#include <cuda_fp16.h>
#include <math.h>
#include <stdint.h>

// Problem constants (fixed shapes from reference)
#define H 112
#define W 112
#define HW 12544
#define CIN 64
#define OUTC 64
#define NB 8
#define NOFF 27          // 3*K*K
#define KK 576           // CIN * 9

// Scratch (static __device__ — no runtime allocation)
__device__ __align__(16) uint16_t g_xt[NB * HW * CIN];   // x in NHWC fp16 [N][H][W][C]
__device__ __align__(16) uint16_t g_wtt[9 * 64 * 64];    // main weights [t][o][c], fp16
__device__ __align__(16) uint16_t g_owtt[9 * 32 * 64];   // offset weights [t][oc(pad32)][c], fp16

#define MMA_F16(d, a0, a1, a2, a3, b0, b1)                                    \
    asm volatile("mma.sync.aligned.m16n8k16.row.col.f32.f16.f16.f32 "         \
        "{%0,%1,%2,%3}, {%4,%5,%6,%7}, {%8,%9}, {%0,%1,%2,%3};"               \
        : "+f"((d)[0]), "+f"((d)[1]), "+f"((d)[2]), "+f"((d)[3])              \
        : "r"(a0), "r"(a1), "r"(a2), "r"(a3), "r"(b0), "r"(b1))

// pack 2 floats -> half2 bits
__device__ __forceinline__ uint32_t f2h2(float lo, float hi) {
    __half2 h = __floats2half2_rn(lo, hi);
    return *(uint32_t*)&h;
}

// ---------------------------------------------------------------------------
// Kernel 0: weight prep (both convs -> per-tap [rows][c] fp16 layouts)
// ---------------------------------------------------------------------------
__global__ void k_wprep(const float* __restrict__ w, const float* __restrict__ ow) {
    int idx = blockIdx.x * 256 + threadIdx.x;     // 0..36863
    if (idx < 9 * 32 * 64) {
        int t = idx >> 11, oc = (idx >> 6) & 31, c = idx & 63;
        float v = (oc < NOFF) ? ow[oc * KK + c * 9 + t] : 0.f;
        __half h = __float2half_rn(v);
        g_owtt[idx] = *(uint16_t*)&h;
    }
    {
        int t = idx >> 12, o = (idx >> 6) & 63, c = idx & 63;
        float v = w[o * KK + c * 9 + t];
        __half h = __float2half_rn(v);
        g_wtt[idx] = *(uint16_t*)&h;
    }
}

// ---------------------------------------------------------------------------
// Kernel 1: NCHW f32 -> NHWC fp16. Block: 64 ch x 32 px, 256 threads.
// ---------------------------------------------------------------------------
__global__ void k_nhwc(const float* __restrict__ x) {
    __shared__ float tile[64][33];
    const int n = blockIdx.z;
    const int p0 = blockIdx.x * 32;
    const float* xn = x + (size_t)n * CIN * HW;
    uint16_t* xtn = g_xt + (size_t)n * HW * CIN;
    const int tx = threadIdx.x & 31, ty = threadIdx.x >> 5;   // 32x8
    #pragma unroll
    for (int i = 0; i < 64; i += 8)
        tile[ty + i][tx] = xn[(size_t)(ty + i) * HW + p0 + tx];
    __syncthreads();
    const int p = threadIdx.x >> 3, c8 = (threadIdx.x & 7) * 8;
    uint4 u;
    u.x = f2h2(tile[c8 + 0][p], tile[c8 + 1][p]);
    u.y = f2h2(tile[c8 + 2][p], tile[c8 + 3][p]);
    u.z = f2h2(tile[c8 + 4][p], tile[c8 + 5][p]);
    u.w = f2h2(tile[c8 + 6][p], tile[c8 + 7][p]);
    *(uint4*)(xtn + (size_t)(p0 + p) * CIN + c8) = u;
}

// ---------------------------------------------------------------------------
// Kernel 2 (fused): offset conv (fp16 mma) + deformable sampling + main GEMM.
// Tile: 16 wo x 4 ho = 64 px, 128 threads (4 warps), 5 CTAs/SM.
//
// SMEM (bytes), row stride 72 halves = 144 B:
//   [0     ,  9216) val_h [64][72] half   | phase1: patch [108][72] half
//   [9216  , 18432) w_h   [64][72] half   |         (15552 B, spills into w_h)
//   [18432 , 25600) raw_s [64][28] f32    | phase1: owt_h [32][72] half (4608 B)
//   [25600 , 26624) cw_s  [64] float4
//   [26624 , 27648) ci_s  [64] int4
//   [27648 , 27904) bs    [64] f32
//
// Phase 1: fp16 patch copy -> 9-tap fp16 mma offset conv -> raw_s[px][27]
// Phase 2: per tap: corners; fp16 NHWC gather (8ch/lane) -> val_h; m16n8k16
//          main GEMM (warp = 32 px x 32 o)
// ---------------------------------------------------------------------------
__global__ void __launch_bounds__(128, 5)
k_main(const float* __restrict__ bias, const float* __restrict__ ob,
       float* __restrict__ out) {
    extern __shared__ unsigned char sm[];
    uint16_t* val_h = (uint16_t*)sm;                 // [64][72]
    uint16_t* w_h   = (uint16_t*)(sm + 9216);        // [64][72]
    float*    raw_s = (float*)(sm + 18432);          // [64][28]
    uint16_t* owt_h = (uint16_t*)(sm + 18432);       // [32][72] (phase 1)
    uint16_t* patch = (uint16_t*)sm;                 // [108][72] (phase 1)
    float4*   cw_s  = (float4*)(sm + 25600);         // [64]
    int4*     ci_s  = (int4*)(sm + 26624);           // [64]
    float*    bs    = (float*)(sm + 27648);          // [64]

    const int tid = threadIdx.x;
    const int wo0 = blockIdx.x * 16, ho0 = blockIdx.y * 4, n = blockIdx.z;
    const int lane = tid & 31, warp = tid >> 5;
    const uint16_t* xtn = g_xt + (size_t)n * (HW * CIN);

    // mma lane mapping (shared by both phases)
    const int g = lane >> 2, ti = lane & 3;

    // ======================= PHASE 1: offset conv ==========================
    // patch copy: 108 pos x 8 groups (8 halves) = 864 tasks, pure uint4 copy
    for (int i = tid; i < 864; i += 128) {
        int pos = i >> 3, q8 = (i & 7) * 8;
        int gy = ho0 - 1 + pos / 18, gx = wo0 - 1 + pos % 18;
        uint4 u = make_uint4(0u, 0u, 0u, 0u);
        if (gy >= 0 && gy < H && gx >= 0 && gx < W)
            u = *(const uint4*)(xtn + (size_t)(gy * W + gx) * CIN + q8);
        *(uint4*)(patch + pos * 72 + q8) = u;
    }

    float aoff[4][4];
    #pragma unroll
    for (int j = 0; j < 4; j++)
        #pragma unroll
        for (int i = 0; i < 4; i++) aoff[j][i] = 0.f;

    for (int t = 0; t < 9; t++) {
        __syncthreads();   // patch ready (t==0) / previous mma done (t>0)
        // owt tile t -> owt_h [32][72]
        {
            const float4* src = (const float4*)(g_owtt + t * 2048);
            #pragma unroll
            for (int i = 0; i < 2; i++) {
                int q = tid + i * 128;               // 0..255 (16B = 8 halves)
                float4 v = src[q];
                *(float4*)(owt_h + (q >> 3) * 72 + (q & 7) * 8) = v;
            }
        }
        __syncthreads();

        const int base = (warp + t / 3) * 18 + (t % 3);
        #pragma unroll
        for (int s = 0; s < 4; s++) {
            const int ko = 16 * s + 2 * ti;
            const uint16_t* ap0 = patch + (base + g) * 72 + ko;
            const uint16_t* ap1 = patch + (base + g + 8) * 72 + ko;
            uint32_t a0 = *(const uint32_t*)ap0;
            uint32_t a2 = *(const uint32_t*)(ap0 + 8);
            uint32_t a1 = *(const uint32_t*)ap1;
            uint32_t a3 = *(const uint32_t*)(ap1 + 8);
            #pragma unroll
            for (int j = 0; j < 4; j++) {
                const uint16_t* bp = owt_h + (j * 8 + g) * 72 + ko;
                uint32_t b0 = *(const uint32_t*)bp;
                uint32_t b1 = *(const uint32_t*)(bp + 8);
                MMA_F16(aoff[j], a0, a1, a2, a3, b0, b1);
            }
        }
    }
    __syncthreads();   // last tap's mma done before raw_s overwrites owt_h

    // write raw_s[px][27] (+ offset bias); warp w owns px rows w*16+g, +8
    {
        const int r0 = warp * 16 + g, r1 = warp * 16 + 8 + g;
        #pragma unroll
        for (int j = 0; j < 4; j++) {
            int oc0 = 8 * j + 2 * ti;
            if (oc0 < NOFF) {
                float b = ob[oc0];
                raw_s[r0 * 28 + oc0] = aoff[j][0] + b;
                raw_s[r1 * 28 + oc0] = aoff[j][2] + b;
            }
            if (oc0 + 1 < NOFF) {
                float b = ob[oc0 + 1];
                raw_s[r0 * 28 + oc0 + 1] = aoff[j][1] + b;
                raw_s[r1 * 28 + oc0 + 1] = aoff[j][3] + b;
            }
        }
    }
    if (tid < 64) bs[tid] = bias[tid];

    // ======================= PHASE 2: main conv ============================
    const int sub = lane >> 3;                  // 0..3 (4 px per pass)
    const int c8 = (lane & 7) * 8;              // 8 channels per lane
    const int px0 = (warp & 1) * 32;
    const int o0  = (warp >> 1) * 32;

    float acc[2][4][4];
    #pragma unroll
    for (int mt = 0; mt < 2; mt++)
        #pragma unroll
        for (int j = 0; j < 4; j++)
            #pragma unroll
            for (int i = 0; i < 4; i++) acc[mt][j][i] = 0.f;

    for (int t = 0; t < 9; t++) {
        __syncthreads();   // raw_s ready (t==0) / previous stage C done (t>0)
        // ---- stage A: weights -> w_h (72-stride); corners from raw_s ----
        {
            const float4* wsrc = (const float4*)(g_wtt + t * 4096);
            #pragma unroll
            for (int i = 0; i < 4; i++) {
                int q = tid + i * 128;               // 0..511 (16B = 8 halves)
                float4 v = wsrc[q];
                *(float4*)(w_h + (q >> 3) * 72 + (q & 7) * 8) = v;
            }
        }
        if (tid < 64) {
            const int y = tid >> 4, wxl = tid & 15;
            const int ho = ho0 + y, wo = wo0 + wxl;
            float dyv = raw_s[tid * 28 + 2 * t];
            float dxv = raw_s[tid * 28 + 2 * t + 1];
            float mv  = raw_s[tid * 28 + 18 + t];
            float m = 1.f / (1.f + expf(-mv));
            float py = dyv + (float)(ho - 1 + t / 3);
            float px = dxv + (float)(wo - 1 + t % 3);
            float y0f = floorf(py), x0f = floorf(px);
            float wy1 = py - y0f, wy0 = 1.f - wy1;
            float wx1 = px - x0f, wx0 = 1.f - wx1;
            int y0 = (int)y0f, x0 = (int)x0f;
            int y1 = y0 + 1, x1 = x0 + 1;
            bool vy0 = (y0 >= 0) && (y0 < H), vy1 = (y1 >= 0) && (y1 < H);
            bool vx0 = (x0 >= 0) && (x0 < W), vx1 = (x1 >= 0) && (x1 < W);
            float w00 = (vy0 && vx0) ? wy0 * wx0 * m : 0.f;
            float w01 = (vy0 && vx1) ? wy0 * wx1 * m : 0.f;
            float w10 = (vy1 && vx0) ? wy1 * wx0 * m : 0.f;
            float w11 = (vy1 && vx1) ? wy1 * wx1 * m : 0.f;
            int yc0 = min(max(y0, 0), H - 1), yc1 = min(max(y1, 0), H - 1);
            int xc0 = min(max(x0, 0), W - 1), xc1 = min(max(x1, 0), W - 1);
            cw_s[tid] = make_float4(w00, w01, w10, w11);
            ci_s[tid] = make_int4(yc0 * W + xc0, yc0 * W + xc1, yc1 * W + xc0, yc1 * W + xc1);
        }
        __syncthreads();

        // ---- stage B: fp16 NHWC gather (8 ch/lane) -> val_h ----
        #pragma unroll
        for (int it = 0; it < 4; it++) {
            int px = warp * 16 + it * 4 + sub;       // 0..63
            float4 w4 = cw_s[px];
            int4 i4 = ci_s[px];
            uint4 q0 = *(const uint4*)(xtn + (size_t)i4.x * CIN + c8);
            uint4 q1 = *(const uint4*)(xtn + (size_t)i4.y * CIN + c8);
            uint4 q2 = *(const uint4*)(xtn + (size_t)i4.z * CIN + c8);
            uint4 q3 = *(const uint4*)(xtn + (size_t)i4.w * CIN + c8);
            uint4 r;
            uint32_t* rp = (uint32_t*)&r;
            const uint32_t* p0 = (const uint32_t*)&q0;
            const uint32_t* p1 = (const uint32_t*)&q1;
            const uint32_t* p2 = (const uint32_t*)&q2;
            const uint32_t* p3 = (const uint32_t*)&q3;
            #pragma unroll
            for (int j = 0; j < 4; j++) {
                float2 a = __half22float2(*(const __half2*)&p0[j]);
                float2 b = __half22float2(*(const __half2*)&p1[j]);
                float2 c = __half22float2(*(const __half2*)&p2[j]);
                float2 d = __half22float2(*(const __half2*)&p3[j]);
                float vx = fmaf(w4.w, d.x, fmaf(w4.z, c.x, fmaf(w4.y, b.x, w4.x * a.x)));
                float vy = fmaf(w4.w, d.y, fmaf(w4.z, c.y, fmaf(w4.y, b.y, w4.x * a.y)));
                rp[j] = f2h2(vx, vy);
            }
            *(uint4*)(val_h + px * 72 + c8) = r;
        }
        __syncthreads();

        // ---- stage C: m16n8k16 fp16 mma, warp tile 32 px x 32 o ----
        #pragma unroll
        for (int s = 0; s < 4; s++) {
            const int ko = 16 * s + 2 * ti;
            #pragma unroll
            for (int mt = 0; mt < 2; mt++) {
                const uint16_t* ap0 = val_h + (px0 + 16 * mt + g) * 72 + ko;
                const uint16_t* ap1 = val_h + (px0 + 16 * mt + g + 8) * 72 + ko;
                uint32_t a0 = *(const uint32_t*)ap0;
                uint32_t a2 = *(const uint32_t*)(ap0 + 8);
                uint32_t a1 = *(const uint32_t*)ap1;
                uint32_t a3 = *(const uint32_t*)(ap1 + 8);
                #pragma unroll
                for (int j = 0; j < 4; j++) {
                    const uint16_t* bp = w_h + (o0 + 8 * j + g) * 72 + ko;
                    uint32_t b0 = *(const uint32_t*)bp;
                    uint32_t b1 = *(const uint32_t*)(bp + 8);
                    MMA_F16(acc[mt][j], a0, a1, a2, a3, b0, b1);
                }
            }
        }
    }

    // ---- epilogue: D frags + bias -> out (NCHW) ----
    #pragma unroll
    for (int mt = 0; mt < 2; mt++) {
        const int ho = ho0 + 2 * (warp & 1) + mt;
        float* op = out + (((size_t)n * OUTC) * H + ho) * W + wo0;
        #pragma unroll
        for (int j = 0; j < 4; j++) {
            int oc = o0 + 8 * j + 2 * ti;
            float b0v = bs[oc], b1v = bs[oc + 1];
            op[(size_t)oc * HW + g]            = acc[mt][j][0] + b0v;
            op[(size_t)(oc + 1) * HW + g]      = acc[mt][j][1] + b1v;
            op[(size_t)oc * HW + g + 8]        = acc[mt][j][2] + b0v;
            op[(size_t)(oc + 1) * HW + g + 8]  = acc[mt][j][3] + b1v;
        }
    }
}

// ---------------------------------------------------------------------------
extern "C" void kernel_launch(void* const* d_in, const int* in_sizes, int n_in,
                              void* d_out, int out_size) {
    (void)in_sizes; (void)n_in; (void)out_size;
    const float* x        = (const float*)d_in[0];
    const float* weight   = (const float*)d_in[1];
    const float* bias     = (const float*)d_in[2];
    const float* offset_w = (const float*)d_in[3];
    const float* offset_b = (const float*)d_in[4];
    float* out = (float*)d_out;

    cudaFuncSetAttribute(k_main, cudaFuncAttributeMaxDynamicSharedMemorySize, 27904);

    k_wprep<<<144, 256>>>(weight, offset_w);
    k_nhwc<<<dim3(392, 1, 8), 256>>>(x);
    k_main<<<dim3(7, 28, 8), 128, 27904>>>(bias, offset_b, out);
}